// round 12
// baseline (speedup 1.0000x reference)
#include <cuda_runtime.h>
#include <cuda_bf16.h>
#include <cuda_fp16.h>
#include <stdint.h>
#include <math.h>

// Problem constants
#define B_  4
#define T_  2048
#define D_  1024
#define H_  16
#define HD_ 64
#define F_  128
#define C_  64
#define N_  32
#define BT_ (B_*T_)        // 8192
#define BHT_ (B_*H_*T_)    // 131072
#define NCHUNK_ (B_*H_*N_) // 2048

// ---------------- scratch (device globals) ----------------------------------
__device__ float g_kv[NCHUNK_*F_*HD_];          // kv^T per chunk: [d][f]
__device__ __half g_ST [NCHUNK_*F_*HD_];        // S_excl^T single fp16
__device__ __half g_qfh[BHT_*F_];               // q features single fp16
__device__ __half g_kfh[BHT_*F_];               // k features single fp16
__device__ __half g_vh [BT_*D_];                // v single fp16
__device__ __half g_xh [BT_*D_];                // x single fp16
__device__ __half g_oh [BT_*D_];                // attention out single fp16
__device__ __half g_wT [3*D_*D_];               // fused qkv weights, fp16 single
__device__ __half g_woT[D_*D_];                 // o weights, fp16 single

// ---------------- PTX helpers ------------------------------------------------
__device__ __forceinline__ uint32_t smem_u32(const void* p) {
    uint32_t a;
    asm("{ .reg .u64 t; cvta.to.shared.u64 t, %1; cvt.u32.u64 %0, t; }" : "=r"(a) : "l"(p));
    return a;
}
__device__ __forceinline__ void cp_async16(uint32_t saddr, const void* gaddr) {
    asm volatile("cp.async.cg.shared.global [%0], [%1], 16;" :: "r"(saddr), "l"(gaddr));
}
__device__ __forceinline__ void cp_commit() {
    asm volatile("cp.async.commit_group;" ::: "memory");
}
template <int NN>
__device__ __forceinline__ void cp_wait() {
    asm volatile("cp.async.wait_group %0;" :: "n"(NN) : "memory");
}
__device__ __forceinline__ void ldm_x4(uint32_t addr, uint32_t& r0, uint32_t& r1,
                                       uint32_t& r2, uint32_t& r3) {
    asm volatile("ldmatrix.sync.aligned.m8n8.x4.shared.b16 {%0,%1,%2,%3}, [%4];"
                 : "=r"(r0), "=r"(r1), "=r"(r2), "=r"(r3) : "r"(addr));
}
__device__ __forceinline__ void mma16816h(float& d0, float& d1, float& d2, float& d3,
                                          uint32_t a0, uint32_t a1, uint32_t a2, uint32_t a3,
                                          uint32_t b0, uint32_t b1) {
    asm volatile("mma.sync.aligned.m16n8k16.row.col.f32.f16.f16.f32 "
                 "{%0,%1,%2,%3}, {%4,%5,%6,%7}, {%8,%9}, {%0,%1,%2,%3};"
                 : "+f"(d0), "+f"(d1), "+f"(d2), "+f"(d3)
                 : "r"(a0), "r"(a1), "r"(a2), "r"(a3), "r"(b0), "r"(b1));
}

// ---------------- weight prep: fold/transpose -> fp16, z-dispatched ----------
__global__ __launch_bounds__(256)
void weightprep_kernel(const float* __restrict__ wq, const float* __restrict__ wk,
                       const float* __restrict__ wv, const float* __restrict__ wo,
                       const float* __restrict__ hqw, const float* __restrict__ hkw,
                       __half* __restrict__ wT, __half* __restrict__ woT)
{
    extern __shared__ float fsm[];
    float* Wb = fsm;               // [128][65]
    float* hh = fsm + 128*65;      // [64][64]
    const int z = blockIdx.z;
    const float* W   = (z==0) ? wq : (z==1) ? wk : (z==2) ? wv : wo;
    const float* hhw = (z==0) ? hqw : (z==1) ? hkw : nullptr;
    __half* dst = (z==3) ? woT : wT;
    const int rowOff = (z==0) ? 0 : (z==1) ? 1024 : (z==2) ? 2048 : 0;

    const int h = blockIdx.x, kb = blockIdx.y;
    const int tid = threadIdx.x;
    for (int i = tid; i < 8192; i += 256) {
        int r = i >> 6, d = i & 63;
        Wb[r*65 + d] = W[(size_t)(kb*128 + r)*D_ + h*64 + d];
    }
    if (hhw)
        for (int i = tid; i < 4096; i += 256) hh[i] = hhw[i];
    __syncthreads();

    const int kk = tid & 127;
    const int e0 = (tid >> 7) * 32;
    float acc[32];
    if (hhw) {
        #pragma unroll
        for (int e = 0; e < 32; e++) acc[e] = 0.f;
        for (int d = 0; d < 64; d++) {
            float wv2 = Wb[kk*65 + d];
            #pragma unroll
            for (int e = 0; e < 32; e++)
                acc[e] = fmaf(wv2, hh[(e0+e)*64 + d], acc[e]);
        }
    } else {
        #pragma unroll
        for (int e = 0; e < 32; e++) acc[e] = Wb[kk*65 + e0 + e];
    }
    #pragma unroll
    for (int e = 0; e < 32; e++) {
        size_t idx = (size_t)(rowOff + h*64 + e0 + e)*D_ + kb*128 + kk;
        dst[idx] = __float2half_rn(acc[e]);
    }
}

// ---------------- fused add + RMSNorm -> resid + fp16 x ----------------------
__global__ __launch_bounds__(256)
void addnorm_kernel(const float* __restrict__ hs, const float* __restrict__ res,
                    const float* __restrict__ w, float* __restrict__ resid_out,
                    __half* __restrict__ xh, int rowOff)
{
    __shared__ float red[8];
    const int row = blockIdx.x + rowOff;
    const int t = threadIdx.x;
    const float4* h4 = (const float4*)(hs  + (size_t)row*D_);
    const float4* r4 = (const float4*)(res + (size_t)row*D_);
    float4*      ro4 = (float4*)(resid_out + (size_t)row*D_);

    float4 h = h4[t], r = r4[t];
    float4 s = make_float4(h.x+r.x, h.y+r.y, h.z+r.z, h.w+r.w);
    ro4[t] = s;
    float ss = s.x*s.x + s.y*s.y + s.z*s.z + s.w*s.w;
    #pragma unroll
    for (int o = 16; o; o >>= 1) ss += __shfl_xor_sync(0xffffffffu, ss, o);
    if ((t & 31) == 0) red[t >> 5] = ss;
    __syncthreads();
    float tot = 0.f;
    #pragma unroll
    for (int i = 0; i < 8; i++) tot += red[i];
    float rstd = rsqrtf(tot * (1.0f/1024.0f) + 1e-5f);
    float4 wv = ((const float4*)w)[t];
    size_t idx = (size_t)row*D_ + t*4;
    *(__half2*)(xh+idx)   = __halves2half2(__float2half_rn(s.x*rstd*wv.x),
                                           __float2half_rn(s.y*rstd*wv.y));
    *(__half2*)(xh+idx+2) = __halves2half2(__float2half_rn(s.z*rstd*wv.z),
                                           __float2half_rn(s.w*rstd*wv.w));
}

// ---------------- fp16 fused QKV GEMM + hedgehog epilogue ---------------------
// Single fp16 A and W. K-tile 64, pitch 144, 3-stage pipeline, 16 barriers total.
#define GP 144
#define MAT_BYTES (128*GP)               // 18432
#define STAGEB (2*MAT_BYTES)             // 36864
#define GSMEM (3*STAGEB)                 // 110592

__global__ __launch_bounds__(256, 2)
void gemm_qkv(const __half* __restrict__ Ah, const __half* __restrict__ W,
              const float* __restrict__ biasq, const float* __restrict__ biask,
              __half* __restrict__ Qfh, __half* __restrict__ Kfh,
              __half* __restrict__ Vh)
{
    extern __shared__ __align__(16) char smem[];
    const uint32_t sbase = smem_u32(smem);
    const int tid = threadIdx.x, wid = tid >> 5, lane = tid & 31;
    const int bx = blockIdx.x, by = blockIdx.y;
    const int wm = wid & 1, wn = wid >> 1;

    const int lrow = tid >> 1;
    const int lc   = (tid & 1) * 4;
    const size_t gA = (size_t)(by*128 + lrow) * D_;
    const size_t gB = (size_t)(bx*128 + lrow) * D_;
    const uint32_t sRow = (uint32_t)lrow * GP;

    float acc[4][4][4];
    #pragma unroll
    for (int i = 0; i < 4; i++)
        #pragma unroll
        for (int j = 0; j < 4; j++)
            #pragma unroll
            for (int l = 0; l < 4; l++) acc[i][j][l] = 0.f;

    #define PREFETCH(kt, buf) do {                                              \
        const int k0 = (kt) * 64;                                               \
        const uint32_t b0 = sbase + (uint32_t)(buf) * STAGEB;                   \
        _Pragma("unroll")                                                       \
        for (int u = 0; u < 4; u++) {                                           \
            const int c = lc + u;                                               \
            const uint32_t so = sRow + (uint32_t)c * 16;                        \
            const size_t go = (size_t)k0 + c * 8;                               \
            cp_async16(b0 + 0*MAT_BYTES + so, Ah + gA + go);                    \
            cp_async16(b0 + 1*MAT_BYTES + so, W  + gB + go);                    \
        }                                                                       \
        cp_commit();                                                            \
    } while (0)

    PREFETCH(0, 0);
    PREFETCH(1, 1);

    const uint32_t aRow = (uint32_t)(wm*64 + (lane & 15)) * GP + (uint32_t)(lane >> 4) * 16;
    const uint32_t bRow = (uint32_t)(wn*32 + ((lane >> 4) & 1)*8 + (lane & 7)) * GP
                        + (uint32_t)((lane >> 3) & 1) * 16;

    const int TILES = D_ / 64;   // 16
    int buf = 0;
    #pragma unroll 1
    for (int kt = 0; kt < TILES; kt++) {
        if (kt == TILES - 1) cp_wait<0>(); else cp_wait<1>();
        __syncthreads();
        if (kt + 2 < TILES) {
            int b2 = buf + 2; if (b2 >= 3) b2 -= 3;
            PREFETCH(kt + 2, b2);
        }
        const uint32_t sb = sbase + (uint32_t)buf * STAGEB;

        #pragma unroll
        for (int kk = 0; kk < 4; kk++) {
            const uint32_t koff = (uint32_t)kk * 32;
            uint32_t bw[2][4];
            #pragma unroll
            for (int nt2 = 0; nt2 < 2; nt2++) {
                const uint32_t ba = bRow + (uint32_t)nt2 * 16 * GP + koff;
                ldm_x4(sb + 1*MAT_BYTES + ba, bw[nt2][0], bw[nt2][1], bw[nt2][2], bw[nt2][3]);
            }
            #pragma unroll
            for (int mt = 0; mt < 4; mt++) {
                const uint32_t aa = aRow + (uint32_t)mt * 16 * GP + koff;
                uint32_t ah[4];
                ldm_x4(sb + aa, ah[0], ah[1], ah[2], ah[3]);
                #pragma unroll
                for (int nt = 0; nt < 4; nt++) {
                    const uint32_t* bp = &bw[nt >> 1][(nt & 1) * 2];
                    float* d = acc[mt][nt];
                    mma16816h(d[0], d[1], d[2], d[3], ah[0], ah[1], ah[2], ah[3], bp[0], bp[1]);
                }
            }
        }
        buf++; if (buf == 3) buf = 0;
    }
    #undef PREFETCH
    __syncthreads();    // smem reuse below

    const int g = lane >> 2, tq = lane & 3;

    if (bx < 16) {
        // -------- hedgehog epilogue: bias + softmax([y,-y]) -> fp16 ----------
        const int isQ = (bx < 8);
        const float* bias = isQ ? biasq : biask;
        const float scale = isQ ? 0.08838834764831845f : 1.0f;
        __half* fh = isQ ? Qfh : Kfh;
        float* smax = (float*)smem;          // [4][128]
        float* ssum = smax + 512;            // [4][128]
        #pragma unroll
        for (int mt = 0; mt < 4; mt++) {
            float pm0 = 0.f, pm1 = 0.f;
            #pragma unroll
            for (int nt = 0; nt < 4; nt++) {
                const int cb = (wn*32 + nt*8 + tq*2) & 63;
                const float b0 = bias[cb], b1 = bias[cb + 1];
                float* d = acc[mt][nt];
                d[0] += b0; d[1] += b1; d[2] += b0; d[3] += b1;
                pm0 = fmaxf(pm0, fmaxf(fabsf(d[0]), fabsf(d[1])));
                pm1 = fmaxf(pm1, fmaxf(fabsf(d[2]), fabsf(d[3])));
            }
            pm0 = fmaxf(pm0, __shfl_xor_sync(0xffffffffu, pm0, 1));
            pm0 = fmaxf(pm0, __shfl_xor_sync(0xffffffffu, pm0, 2));
            pm1 = fmaxf(pm1, __shfl_xor_sync(0xffffffffu, pm1, 1));
            pm1 = fmaxf(pm1, __shfl_xor_sync(0xffffffffu, pm1, 2));
            if (tq == 0) {
                smax[wn*128 + wm*64 + mt*16 + g]     = pm0;
                smax[wn*128 + wm*64 + mt*16 + g + 8] = pm1;
            }
        }
        __syncthreads();
        float mrow[4][2];
        #pragma unroll
        for (int mt = 0; mt < 4; mt++) {
            #pragma unroll
            for (int half = 0; half < 2; half++) {
                const int r = wm*64 + mt*16 + g + half*8;
                mrow[mt][half] = fmaxf(smax[wn*128 + r], smax[(wn^1)*128 + r]);
            }
        }
        #pragma unroll
        for (int mt = 0; mt < 4; mt++) {
            float s0 = 0.f, s1 = 0.f;
            #pragma unroll
            for (int nt = 0; nt < 4; nt++) {
                const float* d = acc[mt][nt];
                s0 += __expf(d[0]-mrow[mt][0]) + __expf(-d[0]-mrow[mt][0])
                    + __expf(d[1]-mrow[mt][0]) + __expf(-d[1]-mrow[mt][0]);
                s1 += __expf(d[2]-mrow[mt][1]) + __expf(-d[2]-mrow[mt][1])
                    + __expf(d[3]-mrow[mt][1]) + __expf(-d[3]-mrow[mt][1]);
            }
            s0 += __shfl_xor_sync(0xffffffffu, s0, 1);
            s0 += __shfl_xor_sync(0xffffffffu, s0, 2);
            s1 += __shfl_xor_sync(0xffffffffu, s1, 1);
            s1 += __shfl_xor_sync(0xffffffffu, s1, 2);
            if (tq == 0) {
                ssum[wn*128 + wm*64 + mt*16 + g]     = s0;
                ssum[wn*128 + wm*64 + mt*16 + g + 8] = s1;
            }
        }
        __syncthreads();
        const int hloc = (bx & 7)*2 + (wn >> 1);
        #pragma unroll
        for (int mt = 0; mt < 4; mt++) {
            #pragma unroll
            for (int half = 0; half < 2; half++) {
                const int r = wm*64 + mt*16 + g + half*8;
                const float z = ssum[wn*128 + r] + ssum[(wn^1)*128 + r];
                const float inv = scale / z;
                const float mm = mrow[mt][half];
                const int rowg = by*128 + r;
                const int bb = rowg >> 11, tt = rowg & 2047;
                const size_t base = ((size_t)(bb*H_ + hloc)*T_ + tt)*F_;
                #pragma unroll
                for (int nt = 0; nt < 4; nt++) {
                    const int f = (wn*32 + nt*8 + tq*2) & 63;
                    const float y0 = acc[mt][nt][half*2], y1 = acc[mt][nt][half*2+1];
                    const float p0 = __expf(y0 - mm)*inv,  p1 = __expf(y1 - mm)*inv;
                    const float n0 = __expf(-y0 - mm)*inv, n1 = __expf(-y1 - mm)*inv;
                    *(__half2*)(fh + base + f) =
                        __halves2half2(__float2half_rn(p0), __float2half_rn(p1));
                    *(__half2*)(fh + base + 64 + f) =
                        __halves2half2(__float2half_rn(n0), __float2half_rn(n1));
                }
            }
        }
    } else {
        // -------- v epilogue: single fp16 ----
        const int colbase = (bx - 16)*128;
        #pragma unroll
        for (int mt = 0; mt < 4; mt++) {
            const int r0 = by*128 + wm*64 + mt*16 + g;
            #pragma unroll
            for (int nt = 0; nt < 4; nt++) {
                const int col = colbase + wn*32 + nt*8 + tq*2;
                float* d = acc[mt][nt];
                *(__half2*)(Vh + (size_t)r0*D_ + col) =
                    __halves2half2(__float2half_rn(d[0]), __float2half_rn(d[1]));
                *(__half2*)(Vh + (size_t)(r0+8)*D_ + col) =
                    __halves2half2(__float2half_rn(d[2]), __float2half_rn(d[3]));
            }
        }
    }
}

// ---------------- fp16 GEMM (fp32 out; o-projection, single-x) ---------------
__global__ __launch_bounds__(256, 2)
void gemm_o(const __half* __restrict__ Ah, const __half* __restrict__ W,
            float* __restrict__ Cout)
{
    extern __shared__ __align__(16) char smem[];
    const uint32_t sbase = smem_u32(smem);
    const int tid = threadIdx.x, wid = tid >> 5, lane = tid & 31;
    const int bx = blockIdx.x, by = blockIdx.y;
    const int wm = wid & 1, wn = wid >> 1;

    const int lrow = tid >> 1;
    const int lc   = (tid & 1) * 4;
    const size_t gA = (size_t)(by*128 + lrow) * D_;
    const size_t gB = (size_t)(bx*128 + lrow) * D_;
    const uint32_t sRow = (uint32_t)lrow * GP;

    float acc[4][4][4];
    #pragma unroll
    for (int i = 0; i < 4; i++)
        #pragma unroll
        for (int j = 0; j < 4; j++)
            #pragma unroll
            for (int l = 0; l < 4; l++) acc[i][j][l] = 0.f;

    #define PREFETCH(kt, buf) do {                                              \
        const int k0 = (kt) * 64;                                               \
        const uint32_t b0 = sbase + (uint32_t)(buf) * STAGEB;                   \
        _Pragma("unroll")                                                       \
        for (int u = 0; u < 4; u++) {                                           \
            const int c = lc + u;                                               \
            const uint32_t so = sRow + (uint32_t)c * 16;                        \
            const size_t go = (size_t)k0 + c * 8;                               \
            cp_async16(b0 + 0*MAT_BYTES + so, Ah + gA + go);                    \
            cp_async16(b0 + 1*MAT_BYTES + so, W  + gB + go);                    \
        }                                                                       \
        cp_commit();                                                            \
    } while (0)

    PREFETCH(0, 0);
    PREFETCH(1, 1);

    const uint32_t aRow = (uint32_t)(wm*64 + (lane & 15)) * GP + (uint32_t)(lane >> 4) * 16;
    const uint32_t bRow = (uint32_t)(wn*32 + ((lane >> 4) & 1)*8 + (lane & 7)) * GP
                        + (uint32_t)((lane >> 3) & 1) * 16;

    const int TILES = D_ / 64;
    int buf = 0;
    #pragma unroll 1
    for (int kt = 0; kt < TILES; kt++) {
        if (kt == TILES - 1) cp_wait<0>(); else cp_wait<1>();
        __syncthreads();
        if (kt + 2 < TILES) {
            int b2 = buf + 2; if (b2 >= 3) b2 -= 3;
            PREFETCH(kt + 2, b2);
        }
        const uint32_t sb = sbase + (uint32_t)buf * STAGEB;

        #pragma unroll
        for (int kk = 0; kk < 4; kk++) {
            const uint32_t koff = (uint32_t)kk * 32;
            uint32_t bw[2][4];
            #pragma unroll
            for (int nt2 = 0; nt2 < 2; nt2++) {
                const uint32_t ba = bRow + (uint32_t)nt2 * 16 * GP + koff;
                ldm_x4(sb + 1*MAT_BYTES + ba, bw[nt2][0], bw[nt2][1], bw[nt2][2], bw[nt2][3]);
            }
            #pragma unroll
            for (int mt = 0; mt < 4; mt++) {
                const uint32_t aa = aRow + (uint32_t)mt * 16 * GP + koff;
                uint32_t ah[4];
                ldm_x4(sb + aa, ah[0], ah[1], ah[2], ah[3]);
                #pragma unroll
                for (int nt = 0; nt < 4; nt++) {
                    const uint32_t* bp = &bw[nt >> 1][(nt & 1) * 2];
                    float* d = acc[mt][nt];
                    mma16816h(d[0], d[1], d[2], d[3], ah[0], ah[1], ah[2], ah[3], bp[0], bp[1]);
                }
            }
        }
        buf++; if (buf == 3) buf = 0;
    }
    #undef PREFETCH

    const int g = lane >> 2, tq = lane & 3;
    #pragma unroll
    for (int mt = 0; mt < 4; mt++) {
        const int r0 = by*128 + wm*64 + mt*16 + g;
        #pragma unroll
        for (int nt = 0; nt < 4; nt++) {
            const int col = bx*128 + wn*32 + nt*8 + tq*2;
            float* d = acc[mt][nt];
            *(float2*)(Cout + (size_t)r0*D_ + col)     = make_float2(d[0], d[1]);
            *(float2*)(Cout + (size_t)(r0+8)*D_ + col) = make_float2(d[2], d[3]);
        }
    }
}

// ---------------- phase A: kv^T[d][f] = sum_c v[c,d] k[c,f]  (single fp16) ---
#define CKV_KT  0u                         // [128 f][64 c] pitch 144 = 18432
#define CKV_VT  18432u                     // [64 d][64 c] pitch 144 = 9216
#define CKV_SMEM 27648u

__global__ __launch_bounds__(256, 2)
void chunk_kv_kernel(const __half* __restrict__ kfh,
                     const __half* __restrict__ vh,
                     float* __restrict__ kvT)
{
    extern __shared__ __align__(16) char smem[];
    const uint32_t sb = smem_u32(smem);
    const int blk = blockIdx.x;
    const int n = blk & 31, bh = blk >> 5;
    const int b = bh >> 4, h = bh & 15;
    const int tid = threadIdx.x, wid = tid >> 5, lane = tid & 31;

    {
        const int c = tid >> 2, fg = (tid & 3) * 32;
        const size_t src = ((size_t)bh*T_ + n*C_ + c)*F_ + fg;
        union { uint4 u; __half b[8]; } r;
        #pragma unroll
        for (int q = 0; q < 4; q++) {
            r.u = *(const uint4*)(kfh + src + q*8);
            #pragma unroll
            for (int i = 0; i < 8; i++)
                *(__half*)(smem + CKV_KT + (fg+q*8+i)*144 + c*2) = r.b[i];
        }
    }
    {
        const int c = tid >> 2, dg = (tid & 3) * 16;
        const size_t src = ((size_t)(b*T_) + n*C_ + c)*D_ + h*HD_ + dg;
        union { uint4 u; __half b[8]; } r;
        #pragma unroll
        for (int q = 0; q < 2; q++) {
            r.u = *(const uint4*)(vh + src + q*8);
            #pragma unroll
            for (int i = 0; i < 8; i++)
                *(__half*)(smem + CKV_VT + (dg+q*8+i)*144 + c*2) = r.b[i];
        }
    }
    __syncthreads();

    const int wm = wid & 3, wn = wid >> 2;
    float acc[8][4];
    #pragma unroll
    for (int i = 0; i < 8; i++)
        #pragma unroll
        for (int j = 0; j < 4; j++) acc[i][j] = 0.f;

    const uint32_t aBase = sb + CKV_VT + (uint32_t)(wm*16 + (lane & 15))*144
                         + (uint32_t)(lane >> 4)*16;
    const uint32_t bBase = sb + CKV_KT + (uint32_t)(wn*64 + ((lane >> 4) & 1)*8 + (lane & 7))*144
                         + (uint32_t)((lane >> 3) & 1)*16;

    #pragma unroll
    for (int ks = 0; ks < 4; ks++) {
        const uint32_t koff = (uint32_t)ks*32;
        uint32_t ah[4];
        ldm_x4(aBase + koff, ah[0], ah[1], ah[2], ah[3]);
        uint32_t bw[4][4];
        #pragma unroll
        for (int p = 0; p < 4; p++) {
            const uint32_t ba = bBase + (uint32_t)p*16*144 + koff;
            ldm_x4(ba, bw[p][0], bw[p][1], bw[p][2], bw[p][3]);
        }
        #pragma unroll
        for (int nt = 0; nt < 8; nt++) {
            const uint32_t* bp = &bw[nt >> 1][(nt & 1)*2];
            float* d = acc[nt];
            mma16816h(d[0], d[1], d[2], d[3], ah[0], ah[1], ah[2], ah[3], bp[0], bp[1]);
        }
    }
    const int g = lane >> 2, tq = lane & 3;
    float* out = kvT + (size_t)blk * (F_*HD_);
    #pragma unroll
    for (int nt = 0; nt < 8; nt++) {
        const int f = wn*64 + nt*8 + tq*2;
        const int d0 = wm*16 + g;
        *(float2*)(out + (size_t)d0*F_ + f)     = make_float2(acc[nt][0], acc[nt][1]);
        *(float2*)(out + (size_t)(d0+8)*F_ + f) = make_float2(acc[nt][2], acc[nt][3]);
    }
}

// ---------------- phase B: exclusive cumsum -> single fp16 -------------------
__global__ __launch_bounds__(1024)
void kv_scan_kernel(const float* __restrict__ kvT, __half* __restrict__ ST)
{
    const int blk = blockIdx.x;
    const int bh = blk >> 3, seg = blk & 7;
    const int e = seg*1024 + threadIdx.x;
    size_t base = (size_t)bh * N_ * (F_*HD_) + e;
    float acc = 0.f;
    for (int n = 0; n < N_; n++) {
        size_t idx = base + (size_t)n * (F_*HD_);
        ST[idx] = __float2half_rn(acc);
        acc += kvT[idx];
    }
}

// ---------------- phase C: out = q@S_excl + tril(q@k^T)@v  (single fp16) -----
#define CO_Q   0u          // [64 c][128 f] pitch 272 = 17408
#define CO_K   17408u      // k [c][f]; later ST [d][f]
#define CO_VT  34816u      // vT [64 d][64 c] pitch 144 = 9216
#define CO_SC  44032u      // masked scores [64 c][64 m] pitch 144 = 9216
#define CO_SMEM 53248u

__global__ __launch_bounds__(256, 2)
void chunk_out_kernel(const __half* __restrict__ qfh,
                      const __half* __restrict__ kfh,
                      const __half* __restrict__ vh,
                      const __half* __restrict__ ST,
                      __half* __restrict__ oh)
{
    extern __shared__ __align__(16) char smem[];
    const uint32_t sb = smem_u32(smem);
    const int blk = blockIdx.x;
    const int n = blk & 31, bh = blk >> 5;
    const int b = bh >> 4, h = bh & 15;
    const int tid = threadIdx.x, wid = tid >> 5, lane = tid & 31;

    {
        const int c = tid >> 2, fg = (tid & 3) * 32;
        const size_t src = ((size_t)bh*T_ + n*C_ + c)*F_ + fg;
        uint4* dq = (uint4*)(smem + CO_Q + c*272 + fg*2);
        uint4* dk = (uint4*)(smem + CO_K + c*272 + fg*2);
        #pragma unroll
        for (int q = 0; q < 4; q++) {
            dq[q] = *(const uint4*)(qfh + src + q*8);
            dk[q] = *(const uint4*)(kfh + src + q*8);
        }
    }
    {
        const int c = tid >> 2, dg = (tid & 3) * 16;
        const size_t src = ((size_t)(b*T_) + n*C_ + c)*D_ + h*HD_ + dg;
        union { uint4 u; __half bb[8]; } r;
        #pragma unroll
        for (int q = 0; q < 2; q++) {
            r.u = *(const uint4*)(vh + src + q*8);
            #pragma unroll
            for (int i = 0; i < 8; i++)
                *(__half*)(smem + CO_VT + (dg+q*8+i)*144 + c*2) = r.bb[i];
        }
    }
    __syncthreads();

    const int wm = wid & 3, wn = wid >> 2;
    const int g = lane >> 2, tq = lane & 3;

    const uint32_t aQ = sb + CO_Q + (uint32_t)(wm*16 + (lane & 15))*272 + (uint32_t)(lane >> 4)*16;
    const uint32_t bK = sb + CO_K + (uint32_t)(wn*32 + ((lane >> 4) & 1)*8 + (lane & 7))*272
                      + (uint32_t)((lane >> 3) & 1)*16;

    // ---- scores = q @ k^T ----
    float sacc[4][4];
    #pragma unroll
    for (int i = 0; i < 4; i++)
        #pragma unroll
        for (int j = 0; j < 4; j++) sacc[i][j] = 0.f;

    #pragma unroll
    for (int ks = 0; ks < 8; ks++) {
        const uint32_t koff = (uint32_t)ks*32;
        uint32_t ah[4];
        ldm_x4(aQ + koff, ah[0], ah[1], ah[2], ah[3]);
        uint32_t bw[2][4];
        #pragma unroll
        for (int p = 0; p < 2; p++) {
            const uint32_t ba = bK + (uint32_t)p*16*272 + koff;
            ldm_x4(ba, bw[p][0], bw[p][1], bw[p][2], bw[p][3]);
        }
        #pragma unroll
        for (int nt = 0; nt < 4; nt++) {
            const uint32_t* bp = &bw[nt >> 1][(nt & 1)*2];
            float* d = sacc[nt];
            mma16816h(d[0], d[1], d[2], d[3], ah[0], ah[1], ah[2], ah[3], bp[0], bp[1]);
        }
    }
    #pragma unroll
    for (int nt = 0; nt < 4; nt++) {
        const int colb = wn*32 + nt*8 + tq*2;
        const int r0 = wm*16 + g, r1 = r0 + 8;
        float v00 = (colb     <= r0) ? sacc[nt][0] : 0.f;
        float v01 = (colb + 1 <= r0) ? sacc[nt][1] : 0.f;
        float v10 = (colb     <= r1) ? sacc[nt][2] : 0.f;
        float v11 = (colb + 1 <= r1) ? sacc[nt][3] : 0.f;
        *(__half2*)(smem + CO_SC + r0*144 + colb*2) =
            __halves2half2(__float2half_rn(v00), __float2half_rn(v01));
        *(__half2*)(smem + CO_SC + r1*144 + colb*2) =
            __halves2half2(__float2half_rn(v10), __float2half_rn(v11));
    }
    __syncthreads();

    {
        const int d = tid >> 2, fg = (tid & 3) * 32;
        const size_t src = (size_t)blk*(F_*HD_) + d*F_ + fg;
        uint4* dh = (uint4*)(smem + CO_K + d*272 + fg*2);
        #pragma unroll
        for (int q = 0; q < 4; q++)
            dh[q] = *(const uint4*)(ST + src + q*8);
    }
    __syncthreads();

    // ---- out = q @ S_excl + scores @ v ----
    float oacc[4][4];
    #pragma unroll
    for (int i = 0; i < 4; i++)
        #pragma unroll
        for (int j = 0; j < 4; j++) oacc[i][j] = 0.f;

    #pragma unroll
    for (int ks = 0; ks < 8; ks++) {     // inter
        const uint32_t koff = (uint32_t)ks*32;
        uint32_t ah[4];
        ldm_x4(aQ + koff, ah[0], ah[1], ah[2], ah[3]);
        uint32_t bw[2][4];
        #pragma unroll
        for (int p = 0; p < 2; p++) {
            const uint32_t ba = bK + (uint32_t)p*16*272 + koff;
            ldm_x4(ba, bw[p][0], bw[p][1], bw[p][2], bw[p][3]);
        }
        #pragma unroll
        for (int nt = 0; nt < 4; nt++) {
            const uint32_t* bp = &bw[nt >> 1][(nt & 1)*2];
            float* d = oacc[nt];
            mma16816h(d[0], d[1], d[2], d[3], ah[0], ah[1], ah[2], ah[3], bp[0], bp[1]);
        }
    }
    {   // intra
        const uint32_t aS = sb + CO_SC + (uint32_t)(wm*16 + (lane & 15))*144
                          + (uint32_t)(lane >> 4)*16;
        const uint32_t bV = sb + CO_VT + (uint32_t)(wn*32 + ((lane >> 4) & 1)*8 + (lane & 7))*144
                          + (uint32_t)((lane >> 3) & 1)*16;
        #pragma unroll
        for (int ks = 0; ks < 4; ks++) {
            const uint32_t koff = (uint32_t)ks*32;
            uint32_t ah[4];
            ldm_x4(aS + koff, ah[0], ah[1], ah[2], ah[3]);
            uint32_t bw[2][4];
            #pragma unroll
            for (int p = 0; p < 2; p++) {
                const uint32_t ba = bV + (uint32_t)p*16*144 + koff;
                ldm_x4(ba, bw[p][0], bw[p][1], bw[p][2], bw[p][3]);
            }
            #pragma unroll
            for (int nt = 0; nt < 4; nt++) {
                const uint32_t* bp = &bw[nt >> 1][(nt & 1)*2];
                float* d = oacc[nt];
                mma16816h(d[0], d[1], d[2], d[3], ah[0], ah[1], ah[2], ah[3], bp[0], bp[1]);
            }
        }
    }

    // write o single fp16 in [B,T,H*HD] layout
    #pragma unroll
    for (int nt = 0; nt < 4; nt++) {
        const int dcol = wn*32 + nt*8 + tq*2;
        const int r0 = wm*16 + g;
        #pragma unroll
        for (int half = 0; half < 2; half++) {
            const int r = r0 + half*8;
            const size_t oidx = ((size_t)(b*T_) + n*C_ + r)*D_ + h*HD_ + dcol;
            *(__half2*)(oh + oidx) =
                __halves2half2(__float2half_rn(oacc[nt][half*2]),
                               __float2half_rn(oacc[nt][half*2+1]));
        }
    }
}

// ---------------- launcher ----------------------------------------------------
extern "C" void kernel_launch(void* const* d_in, const int* in_sizes, int n_in,
                              void* d_out, int out_size)
{
    const float* hs   = (const float*)d_in[0];
    const float* res  = (const float*)d_in[1];
    const float* nw   = (const float*)d_in[2];
    const float* w_q  = (const float*)d_in[3];
    const float* w_k  = (const float*)d_in[4];
    const float* w_v  = (const float*)d_in[5];
    const float* w_o  = (const float*)d_in[6];
    const float* hqw  = (const float*)d_in[7];
    const float* hqb  = (const float*)d_in[8];
    const float* hkw  = (const float*)d_in[9];
    const float* hkb  = (const float*)d_in[10];
    float* out = (float*)d_out;

    float *pkv;
    __half *pxh, *poh, *pwT, *pwo, *pqfh, *pkfh, *pvh, *pST;
    cudaGetSymbolAddress((void**)&pkv,  g_kv);
    cudaGetSymbolAddress((void**)&pxh,  g_xh);
    cudaGetSymbolAddress((void**)&poh,  g_oh);
    cudaGetSymbolAddress((void**)&pwT,  g_wT);
    cudaGetSymbolAddress((void**)&pwo,  g_woT);
    cudaGetSymbolAddress((void**)&pqfh, g_qfh);
    cudaGetSymbolAddress((void**)&pkfh, g_kfh);
    cudaGetSymbolAddress((void**)&pvh,  g_vh);
    cudaGetSymbolAddress((void**)&pST,  g_ST);

    const int fsmem = (128*65 + 64*64) * sizeof(float);   // 49664
    cudaFuncSetAttribute(weightprep_kernel,
                         cudaFuncAttributeMaxDynamicSharedMemorySize, fsmem);
    cudaFuncSetAttribute(gemm_qkv,
                         cudaFuncAttributeMaxDynamicSharedMemorySize, GSMEM);
    cudaFuncSetAttribute(gemm_o,
                         cudaFuncAttributeMaxDynamicSharedMemorySize, GSMEM);
    cudaFuncSetAttribute(chunk_kv_kernel,
                         cudaFuncAttributeMaxDynamicSharedMemorySize, CKV_SMEM);
    cudaFuncSetAttribute(chunk_out_kernel,
                         cudaFuncAttributeMaxDynamicSharedMemorySize, CO_SMEM);

    // 1) weight prep (fold hedgehog into q/k; transpose v, o) -> fp16
    weightprep_kernel<<<dim3(16, 8, 4), 256, fsmem>>>(w_q, w_k, w_v, w_o, hqw, hkw, pwT, pwo);

    // 2+3) fused add + RMSNorm (two halves -> keeps gemm_qkv as launch #4)
    addnorm_kernel<<<BT_/2, 256>>>(hs, res, nw, out + (size_t)BT_*D_, pxh, 0);
    addnorm_kernel<<<BT_/2, 256>>>(hs, res, nw, out + (size_t)BT_*D_, pxh, BT_/2);

    // 4) fused QKV projection + hedgehog epilogue (all single fp16, KT=64)
    dim3 qkvgrid(24, BT_/128);
    gemm_qkv<<<qkvgrid, 256, GSMEM>>>(pxh, pwT, hqb, hkb, pqfh, pkfh, pvh);

    // 5) chunked linear attention (single fp16 tensor cores)
    chunk_kv_kernel<<<NCHUNK_, 256, CKV_SMEM>>>(pkfh, pvh, pkv);
    kv_scan_kernel<<<512, 1024>>>(pkv, pST);
    chunk_out_kernel<<<NCHUNK_, 256, CO_SMEM>>>(pqfh, pkfh, pvh, pST, poh);

    // 6) output projection (single fp16, KT=64)
    gemm_o<<<dim3(8, BT_/128), 256, GSMEM>>>(poh, pwo, out);
}

// round 13
// speedup vs baseline: 1.0605x; 1.0605x over previous
#include <cuda_runtime.h>
#include <cuda_bf16.h>
#include <cuda_fp16.h>
#include <stdint.h>
#include <math.h>

// Problem constants
#define B_  4
#define T_  2048
#define D_  1024
#define H_  16
#define HD_ 64
#define F_  128
#define C_  64
#define N_  32
#define BT_ (B_*T_)        // 8192
#define BHT_ (B_*H_*T_)    // 131072
#define NCHUNK_ (B_*H_*N_) // 2048

// ---------------- scratch (device globals) ----------------------------------
__device__ __half g_kv [NCHUNK_*F_*HD_];        // kv^T per chunk (fp16)
__device__ __half g_ST [NCHUNK_*F_*HD_];        // S_excl^T single fp16
__device__ __half g_qfh[BHT_*F_];               // q features single fp16
__device__ __half g_kfh[BHT_*F_];               // k features single fp16
__device__ __half g_vh [BT_*D_];                // v single fp16
__device__ __half g_xh [BT_*D_];                // x single fp16
__device__ __half g_oh [BT_*D_];                // attention out single fp16
__device__ __half g_wT [3*D_*D_];               // fused qkv weights, fp16 single
__device__ __half g_woT[D_*D_];                 // o weights, fp16 single

// ---------------- PTX helpers ------------------------------------------------
__device__ __forceinline__ uint32_t smem_u32(const void* p) {
    uint32_t a;
    asm("{ .reg .u64 t; cvta.to.shared.u64 t, %1; cvt.u32.u64 %0, t; }" : "=r"(a) : "l"(p));
    return a;
}
__device__ __forceinline__ void cp_async16(uint32_t saddr, const void* gaddr) {
    asm volatile("cp.async.cg.shared.global [%0], [%1], 16;" :: "r"(saddr), "l"(gaddr));
}
__device__ __forceinline__ void cp_commit() {
    asm volatile("cp.async.commit_group;" ::: "memory");
}
template <int NN>
__device__ __forceinline__ void cp_wait() {
    asm volatile("cp.async.wait_group %0;" :: "n"(NN) : "memory");
}
__device__ __forceinline__ void ldm_x4(uint32_t addr, uint32_t& r0, uint32_t& r1,
                                       uint32_t& r2, uint32_t& r3) {
    asm volatile("ldmatrix.sync.aligned.m8n8.x4.shared.b16 {%0,%1,%2,%3}, [%4];"
                 : "=r"(r0), "=r"(r1), "=r"(r2), "=r"(r3) : "r"(addr));
}
__device__ __forceinline__ void mma16816h(float& d0, float& d1, float& d2, float& d3,
                                          uint32_t a0, uint32_t a1, uint32_t a2, uint32_t a3,
                                          uint32_t b0, uint32_t b1) {
    asm volatile("mma.sync.aligned.m16n8k16.row.col.f32.f16.f16.f32 "
                 "{%0,%1,%2,%3}, {%4,%5,%6,%7}, {%8,%9}, {%0,%1,%2,%3};"
                 : "+f"(d0), "+f"(d1), "+f"(d2), "+f"(d3)
                 : "r"(a0), "r"(a1), "r"(a2), "r"(a3), "r"(b0), "r"(b1));
}

// ---------------- weight prep: fold/transpose -> fp16, z-dispatched ----------
__global__ __launch_bounds__(256)
void weightprep_kernel(const float* __restrict__ wq, const float* __restrict__ wk,
                       const float* __restrict__ wv, const float* __restrict__ wo,
                       const float* __restrict__ hqw, const float* __restrict__ hkw,
                       __half* __restrict__ wT, __half* __restrict__ woT)
{
    extern __shared__ float fsm[];
    float* Wb = fsm;               // [128][65]
    float* hh = fsm + 128*65;      // [64][64]
    const int z = blockIdx.z;
    const float* W   = (z==0) ? wq : (z==1) ? wk : (z==2) ? wv : wo;
    const float* hhw = (z==0) ? hqw : (z==1) ? hkw : nullptr;
    __half* dst = (z==3) ? woT : wT;
    const int rowOff = (z==0) ? 0 : (z==1) ? 1024 : (z==2) ? 2048 : 0;

    const int h = blockIdx.x, kb = blockIdx.y;
    const int tid = threadIdx.x;
    for (int i = tid; i < 8192; i += 256) {
        int r = i >> 6, d = i & 63;
        Wb[r*65 + d] = W[(size_t)(kb*128 + r)*D_ + h*64 + d];
    }
    if (hhw)
        for (int i = tid; i < 4096; i += 256) hh[i] = hhw[i];
    __syncthreads();

    const int kk = tid & 127;
    const int e0 = (tid >> 7) * 32;
    float acc[32];
    if (hhw) {
        #pragma unroll
        for (int e = 0; e < 32; e++) acc[e] = 0.f;
        for (int d = 0; d < 64; d++) {
            float wv2 = Wb[kk*65 + d];
            #pragma unroll
            for (int e = 0; e < 32; e++)
                acc[e] = fmaf(wv2, hh[(e0+e)*64 + d], acc[e]);
        }
    } else {
        #pragma unroll
        for (int e = 0; e < 32; e++) acc[e] = Wb[kk*65 + e0 + e];
    }
    #pragma unroll
    for (int e = 0; e < 32; e++) {
        size_t idx = (size_t)(rowOff + h*64 + e0 + e)*D_ + kb*128 + kk;
        dst[idx] = __float2half_rn(acc[e]);
    }
}

// ---------------- fused add + RMSNorm -> resid + fp16 x ----------------------
__global__ __launch_bounds__(256)
void addnorm_kernel(const float* __restrict__ hs, const float* __restrict__ res,
                    const float* __restrict__ w, float* __restrict__ resid_out,
                    __half* __restrict__ xh, int rowOff)
{
    __shared__ float red[8];
    const int row = blockIdx.x + rowOff;
    const int t = threadIdx.x;
    const float4* h4 = (const float4*)(hs  + (size_t)row*D_);
    const float4* r4 = (const float4*)(res + (size_t)row*D_);
    float4*      ro4 = (float4*)(resid_out + (size_t)row*D_);

    float4 h = h4[t], r = r4[t];
    float4 s = make_float4(h.x+r.x, h.y+r.y, h.z+r.z, h.w+r.w);
    ro4[t] = s;
    float ss = s.x*s.x + s.y*s.y + s.z*s.z + s.w*s.w;
    #pragma unroll
    for (int o = 16; o; o >>= 1) ss += __shfl_xor_sync(0xffffffffu, ss, o);
    if ((t & 31) == 0) red[t >> 5] = ss;
    __syncthreads();
    float tot = 0.f;
    #pragma unroll
    for (int i = 0; i < 8; i++) tot += red[i];
    float rstd = rsqrtf(tot * (1.0f/1024.0f) + 1e-5f);
    float4 wv = ((const float4*)w)[t];
    size_t idx = (size_t)row*D_ + t*4;
    *(__half2*)(xh+idx)   = __halves2half2(__float2half_rn(s.x*rstd*wv.x),
                                           __float2half_rn(s.y*rstd*wv.y));
    *(__half2*)(xh+idx+2) = __halves2half2(__float2half_rn(s.z*rstd*wv.z),
                                           __float2half_rn(s.w*rstd*wv.w));
}

// ---------------- fp16 fused QKV GEMM + hedgehog epilogue ---------------------
// Single fp16 A and W. K-tile 32, pitch 80, 4-stage pipeline, cp_wait<2>.
#define PITCH 40
#define MAT_BYTES (128*PITCH*2)          // 10240
#define STAGEB (2*MAT_BYTES)             // 20480
#define GSMEM (4*STAGEB)                 // 81920

__global__ __launch_bounds__(256, 2)
void gemm_qkv(const __half* __restrict__ Ah, const __half* __restrict__ W,
              const float* __restrict__ biasq, const float* __restrict__ biask,
              __half* __restrict__ Qfh, __half* __restrict__ Kfh,
              __half* __restrict__ Vh)
{
    extern __shared__ __align__(16) char smem[];
    const uint32_t sbase = smem_u32(smem);
    const int tid = threadIdx.x, wid = tid >> 5, lane = tid & 31;
    const int bx = blockIdx.x, by = blockIdx.y;
    const int wm = wid & 1, wn = wid >> 1;

    const int lrow = tid >> 1;
    const int lc   = (tid & 1) * 2;
    const size_t gA = (size_t)(by*128 + lrow) * D_;
    const size_t gB = (size_t)(bx*128 + lrow) * D_;
    const uint32_t sRow = (uint32_t)lrow * 80;

    float acc[4][4][4];
    #pragma unroll
    for (int i = 0; i < 4; i++)
        #pragma unroll
        for (int j = 0; j < 4; j++)
            #pragma unroll
            for (int l = 0; l < 4; l++) acc[i][j][l] = 0.f;

    #define PREFETCH(kt, buf) do {                                              \
        const int k0 = (kt) * 32;                                               \
        const uint32_t b0 = sbase + (uint32_t)(buf) * STAGEB;                   \
        _Pragma("unroll")                                                       \
        for (int u = 0; u < 2; u++) {                                           \
            const int c = lc + u;                                               \
            const uint32_t so = sRow + (uint32_t)c * 16;                        \
            const size_t go = (size_t)k0 + c * 8;                               \
            cp_async16(b0 + 0*MAT_BYTES + so, Ah + gA + go);                    \
            cp_async16(b0 + 1*MAT_BYTES + so, W  + gB + go);                    \
        }                                                                       \
        cp_commit();                                                            \
    } while (0)

    PREFETCH(0, 0);
    PREFETCH(1, 1);
    PREFETCH(2, 2);

    const uint32_t aRow = (uint32_t)(wm*64 + (lane & 15)) * 80 + (uint32_t)(lane >> 4) * 16;
    const uint32_t bRow = (uint32_t)(wn*32 + ((lane >> 4) & 1)*8 + (lane & 7)) * 80
                        + (uint32_t)((lane >> 3) & 1) * 16;

    const int TILES = D_ / 32;   // 32
    int buf = 0;                 // kt % 4
    #pragma unroll 1
    for (int kt = 0; kt < TILES; kt++) {
        if (kt >= TILES - 3) cp_wait<0>(); else cp_wait<2>();
        __syncthreads();
        if (kt + 3 < TILES) {
            int b3 = buf + 3; if (b3 >= 4) b3 -= 4;
            PREFETCH(kt + 3, b3);
        }
        const uint32_t sb = sbase + (uint32_t)buf * STAGEB;

        #pragma unroll
        for (int kk = 0; kk < 2; kk++) {
            const uint32_t koff = (uint32_t)kk * 32;
            uint32_t bw[2][4];
            #pragma unroll
            for (int nt2 = 0; nt2 < 2; nt2++) {
                const uint32_t ba = bRow + (uint32_t)nt2 * 16 * 80 + koff;
                ldm_x4(sb + 1*MAT_BYTES + ba, bw[nt2][0], bw[nt2][1], bw[nt2][2], bw[nt2][3]);
            }
            #pragma unroll
            for (int mt = 0; mt < 4; mt++) {
                const uint32_t aa = aRow + (uint32_t)mt * 16 * 80 + koff;
                uint32_t ah[4];
                ldm_x4(sb + aa, ah[0], ah[1], ah[2], ah[3]);
                #pragma unroll
                for (int nt = 0; nt < 4; nt++) {
                    const uint32_t* bp = &bw[nt >> 1][(nt & 1) * 2];
                    float* d = acc[mt][nt];
                    mma16816h(d[0], d[1], d[2], d[3], ah[0], ah[1], ah[2], ah[3], bp[0], bp[1]);
                }
            }
        }
        buf++; if (buf == 4) buf = 0;
    }
    #undef PREFETCH
    __syncthreads();    // smem reuse below

    const int g = lane >> 2, tq = lane & 3;

    if (bx < 16) {
        // -------- hedgehog epilogue: bias + softmax([y,-y]) -> fp16 ----------
        const int isQ = (bx < 8);
        const float* bias = isQ ? biasq : biask;
        const float scale = isQ ? 0.08838834764831845f : 1.0f;
        __half* fh = isQ ? Qfh : Kfh;
        float* smax = (float*)smem;          // [4][128]
        float* ssum = smax + 512;            // [4][128]
        #pragma unroll
        for (int mt = 0; mt < 4; mt++) {
            float pm0 = 0.f, pm1 = 0.f;
            #pragma unroll
            for (int nt = 0; nt < 4; nt++) {
                const int cb = (wn*32 + nt*8 + tq*2) & 63;
                const float b0 = bias[cb], b1 = bias[cb + 1];
                float* d = acc[mt][nt];
                d[0] += b0; d[1] += b1; d[2] += b0; d[3] += b1;
                pm0 = fmaxf(pm0, fmaxf(fabsf(d[0]), fabsf(d[1])));
                pm1 = fmaxf(pm1, fmaxf(fabsf(d[2]), fabsf(d[3])));
            }
            pm0 = fmaxf(pm0, __shfl_xor_sync(0xffffffffu, pm0, 1));
            pm0 = fmaxf(pm0, __shfl_xor_sync(0xffffffffu, pm0, 2));
            pm1 = fmaxf(pm1, __shfl_xor_sync(0xffffffffu, pm1, 1));
            pm1 = fmaxf(pm1, __shfl_xor_sync(0xffffffffu, pm1, 2));
            if (tq == 0) {
                smax[wn*128 + wm*64 + mt*16 + g]     = pm0;
                smax[wn*128 + wm*64 + mt*16 + g + 8] = pm1;
            }
        }
        __syncthreads();
        float mrow[4][2];
        #pragma unroll
        for (int mt = 0; mt < 4; mt++) {
            #pragma unroll
            for (int half = 0; half < 2; half++) {
                const int r = wm*64 + mt*16 + g + half*8;
                mrow[mt][half] = fmaxf(smax[wn*128 + r], smax[(wn^1)*128 + r]);
            }
        }
        #pragma unroll
        for (int mt = 0; mt < 4; mt++) {
            float s0 = 0.f, s1 = 0.f;
            #pragma unroll
            for (int nt = 0; nt < 4; nt++) {
                const float* d = acc[mt][nt];
                s0 += __expf(d[0]-mrow[mt][0]) + __expf(-d[0]-mrow[mt][0])
                    + __expf(d[1]-mrow[mt][0]) + __expf(-d[1]-mrow[mt][0]);
                s1 += __expf(d[2]-mrow[mt][1]) + __expf(-d[2]-mrow[mt][1])
                    + __expf(d[3]-mrow[mt][1]) + __expf(-d[3]-mrow[mt][1]);
            }
            s0 += __shfl_xor_sync(0xffffffffu, s0, 1);
            s0 += __shfl_xor_sync(0xffffffffu, s0, 2);
            s1 += __shfl_xor_sync(0xffffffffu, s1, 1);
            s1 += __shfl_xor_sync(0xffffffffu, s1, 2);
            if (tq == 0) {
                ssum[wn*128 + wm*64 + mt*16 + g]     = s0;
                ssum[wn*128 + wm*64 + mt*16 + g + 8] = s1;
            }
        }
        __syncthreads();
        const int hloc = (bx & 7)*2 + (wn >> 1);
        #pragma unroll
        for (int mt = 0; mt < 4; mt++) {
            #pragma unroll
            for (int half = 0; half < 2; half++) {
                const int r = wm*64 + mt*16 + g + half*8;
                const float z = ssum[wn*128 + r] + ssum[(wn^1)*128 + r];
                const float inv = scale / z;
                const float mm = mrow[mt][half];
                const int rowg = by*128 + r;
                const int bb = rowg >> 11, tt = rowg & 2047;
                const size_t base = ((size_t)(bb*H_ + hloc)*T_ + tt)*F_;
                #pragma unroll
                for (int nt = 0; nt < 4; nt++) {
                    const int f = (wn*32 + nt*8 + tq*2) & 63;
                    const float y0 = acc[mt][nt][half*2], y1 = acc[mt][nt][half*2+1];
                    const float p0 = __expf(y0 - mm)*inv,  p1 = __expf(y1 - mm)*inv;
                    const float n0 = __expf(-y0 - mm)*inv, n1 = __expf(-y1 - mm)*inv;
                    *(__half2*)(fh + base + f) =
                        __halves2half2(__float2half_rn(p0), __float2half_rn(p1));
                    *(__half2*)(fh + base + 64 + f) =
                        __halves2half2(__float2half_rn(n0), __float2half_rn(n1));
                }
            }
        }
    } else {
        // -------- v epilogue: single fp16 ----
        const int colbase = (bx - 16)*128;
        #pragma unroll
        for (int mt = 0; mt < 4; mt++) {
            const int r0 = by*128 + wm*64 + mt*16 + g;
            #pragma unroll
            for (int nt = 0; nt < 4; nt++) {
                const int col = colbase + wn*32 + nt*8 + tq*2;
                float* d = acc[mt][nt];
                *(__half2*)(Vh + (size_t)r0*D_ + col) =
                    __halves2half2(__float2half_rn(d[0]), __float2half_rn(d[1]));
                *(__half2*)(Vh + (size_t)(r0+8)*D_ + col) =
                    __halves2half2(__float2half_rn(d[2]), __float2half_rn(d[3]));
            }
        }
    }
}

// ---------------- fp16 GEMM (fp32 out; o-projection) --------------------------
__global__ __launch_bounds__(256, 2)
void gemm_o(const __half* __restrict__ Ah, const __half* __restrict__ W,
            float* __restrict__ Cout)
{
    extern __shared__ __align__(16) char smem[];
    const uint32_t sbase = smem_u32(smem);
    const int tid = threadIdx.x, wid = tid >> 5, lane = tid & 31;
    const int bx = blockIdx.x, by = blockIdx.y;
    const int wm = wid & 1, wn = wid >> 1;

    const int lrow = tid >> 1;
    const int lc   = (tid & 1) * 2;
    const size_t gA = (size_t)(by*128 + lrow) * D_;
    const size_t gB = (size_t)(bx*128 + lrow) * D_;
    const uint32_t sRow = (uint32_t)lrow * 80;

    float acc[4][4][4];
    #pragma unroll
    for (int i = 0; i < 4; i++)
        #pragma unroll
        for (int j = 0; j < 4; j++)
            #pragma unroll
            for (int l = 0; l < 4; l++) acc[i][j][l] = 0.f;

    #define PREFETCH(kt, buf) do {                                              \
        const int k0 = (kt) * 32;                                               \
        const uint32_t b0 = sbase + (uint32_t)(buf) * STAGEB;                   \
        _Pragma("unroll")                                                       \
        for (int u = 0; u < 2; u++) {                                           \
            const int c = lc + u;                                               \
            const uint32_t so = sRow + (uint32_t)c * 16;                        \
            const size_t go = (size_t)k0 + c * 8;                               \
            cp_async16(b0 + 0*MAT_BYTES + so, Ah + gA + go);                    \
            cp_async16(b0 + 1*MAT_BYTES + so, W  + gB + go);                    \
        }                                                                       \
        cp_commit();                                                            \
    } while (0)

    PREFETCH(0, 0);
    PREFETCH(1, 1);
    PREFETCH(2, 2);

    const uint32_t aRow = (uint32_t)(wm*64 + (lane & 15)) * 80 + (uint32_t)(lane >> 4) * 16;
    const uint32_t bRow = (uint32_t)(wn*32 + ((lane >> 4) & 1)*8 + (lane & 7)) * 80
                        + (uint32_t)((lane >> 3) & 1) * 16;

    const int TILES = D_ / 32;
    int buf = 0;
    #pragma unroll 1
    for (int kt = 0; kt < TILES; kt++) {
        if (kt >= TILES - 3) cp_wait<0>(); else cp_wait<2>();
        __syncthreads();
        if (kt + 3 < TILES) {
            int b3 = buf + 3; if (b3 >= 4) b3 -= 4;
            PREFETCH(kt + 3, b3);
        }
        const uint32_t sb = sbase + (uint32_t)buf * STAGEB;

        #pragma unroll
        for (int kk = 0; kk < 2; kk++) {
            const uint32_t koff = (uint32_t)kk * 32;
            uint32_t bw[2][4];
            #pragma unroll
            for (int nt2 = 0; nt2 < 2; nt2++) {
                const uint32_t ba = bRow + (uint32_t)nt2 * 16 * 80 + koff;
                ldm_x4(sb + 1*MAT_BYTES + ba, bw[nt2][0], bw[nt2][1], bw[nt2][2], bw[nt2][3]);
            }
            #pragma unroll
            for (int mt = 0; mt < 4; mt++) {
                const uint32_t aa = aRow + (uint32_t)mt * 16 * 80 + koff;
                uint32_t ah[4];
                ldm_x4(sb + aa, ah[0], ah[1], ah[2], ah[3]);
                #pragma unroll
                for (int nt = 0; nt < 4; nt++) {
                    const uint32_t* bp = &bw[nt >> 1][(nt & 1) * 2];
                    float* d = acc[mt][nt];
                    mma16816h(d[0], d[1], d[2], d[3], ah[0], ah[1], ah[2], ah[3], bp[0], bp[1]);
                }
            }
        }
        buf++; if (buf == 4) buf = 0;
    }
    #undef PREFETCH

    const int g = lane >> 2, tq = lane & 3;
    #pragma unroll
    for (int mt = 0; mt < 4; mt++) {
        const int r0 = by*128 + wm*64 + mt*16 + g;
        #pragma unroll
        for (int nt = 0; nt < 4; nt++) {
            const int col = bx*128 + wn*32 + nt*8 + tq*2;
            float* d = acc[mt][nt];
            *(float2*)(Cout + (size_t)r0*D_ + col)     = make_float2(d[0], d[1]);
            *(float2*)(Cout + (size_t)(r0+8)*D_ + col) = make_float2(d[2], d[3]);
        }
    }
}

// ---------------- phase A: kv^T[d][f] = sum_c v[c,d] k[c,f]  (single fp16) ---
#define CKV_KT  0u                         // [128 f][64 c] pitch 144 = 18432
#define CKV_VT  18432u                     // [64 d][64 c] pitch 144 = 9216
#define CKV_SMEM 27648u

__global__ __launch_bounds__(256, 2)
void chunk_kv_kernel(const __half* __restrict__ kfh,
                     const __half* __restrict__ vh,
                     __half* __restrict__ kvT)
{
    extern __shared__ __align__(16) char smem[];
    const uint32_t sb = smem_u32(smem);
    const int blk = blockIdx.x;
    const int n = blk & 31, bh = blk >> 5;
    const int b = bh >> 4, h = bh & 15;
    const int tid = threadIdx.x, wid = tid >> 5, lane = tid & 31;

    {
        const int c = tid >> 2, fg = (tid & 3) * 32;
        const size_t src = ((size_t)bh*T_ + n*C_ + c)*F_ + fg;
        union { uint4 u; __half b[8]; } r;
        #pragma unroll
        for (int q = 0; q < 4; q++) {
            r.u = *(const uint4*)(kfh + src + q*8);
            #pragma unroll
            for (int i = 0; i < 8; i++)
                *(__half*)(smem + CKV_KT + (fg+q*8+i)*144 + c*2) = r.b[i];
        }
    }
    {
        const int c = tid >> 2, dg = (tid & 3) * 16;
        const size_t src = ((size_t)(b*T_) + n*C_ + c)*D_ + h*HD_ + dg;
        union { uint4 u; __half b[8]; } r;
        #pragma unroll
        for (int q = 0; q < 2; q++) {
            r.u = *(const uint4*)(vh + src + q*8);
            #pragma unroll
            for (int i = 0; i < 8; i++)
                *(__half*)(smem + CKV_VT + (dg+q*8+i)*144 + c*2) = r.b[i];
        }
    }
    __syncthreads();

    const int wm = wid & 3, wn = wid >> 2;
    float acc[8][4];
    #pragma unroll
    for (int i = 0; i < 8; i++)
        #pragma unroll
        for (int j = 0; j < 4; j++) acc[i][j] = 0.f;

    const uint32_t aBase = sb + CKV_VT + (uint32_t)(wm*16 + (lane & 15))*144
                         + (uint32_t)(lane >> 4)*16;
    const uint32_t bBase = sb + CKV_KT + (uint32_t)(wn*64 + ((lane >> 4) & 1)*8 + (lane & 7))*144
                         + (uint32_t)((lane >> 3) & 1)*16;

    #pragma unroll
    for (int ks = 0; ks < 4; ks++) {
        const uint32_t koff = (uint32_t)ks*32;
        uint32_t ah[4];
        ldm_x4(aBase + koff, ah[0], ah[1], ah[2], ah[3]);
        uint32_t bw[4][4];
        #pragma unroll
        for (int p = 0; p < 4; p++) {
            const uint32_t ba = bBase + (uint32_t)p*16*144 + koff;
            ldm_x4(ba, bw[p][0], bw[p][1], bw[p][2], bw[p][3]);
        }
        #pragma unroll
        for (int nt = 0; nt < 8; nt++) {
            const uint32_t* bp = &bw[nt >> 1][(nt & 1)*2];
            float* d = acc[nt];
            mma16816h(d[0], d[1], d[2], d[3], ah[0], ah[1], ah[2], ah[3], bp[0], bp[1]);
        }
    }
    const int g = lane >> 2, tq = lane & 3;
    __half* out = kvT + (size_t)blk * (F_*HD_);
    #pragma unroll
    for (int nt = 0; nt < 8; nt++) {
        const int f = wn*64 + nt*8 + tq*2;
        const int d0 = wm*16 + g;
        *(__half2*)(out + (size_t)d0*F_ + f) =
            __halves2half2(__float2half_rn(acc[nt][0]), __float2half_rn(acc[nt][1]));
        *(__half2*)(out + (size_t)(d0+8)*F_ + f) =
            __halves2half2(__float2half_rn(acc[nt][2]), __float2half_rn(acc[nt][3]));
    }
}

// ---------------- phase B: exclusive cumsum (fp32 acc) -> single fp16 --------
__global__ __launch_bounds__(1024)
void kv_scan_kernel(const __half* __restrict__ kvT, __half* __restrict__ ST)
{
    const int blk = blockIdx.x;
    const int bh = blk >> 3, seg = blk & 7;
    const int e = seg*1024 + threadIdx.x;
    size_t base = (size_t)bh * N_ * (F_*HD_) + e;
    float acc = 0.f;
    for (int n = 0; n < N_; n++) {
        size_t idx = base + (size_t)n * (F_*HD_);
        ST[idx] = __float2half_rn(acc);
        acc += __half2float(kvT[idx]);
    }
}

// ---------------- phase C: out = q@S_excl + tril(q@k^T)@v  (single fp16) -----
#define CO_Q   0u          // [64 c][128 f] pitch 272 = 17408
#define CO_K   17408u      // k [c][f]; later ST [d][f]
#define CO_VT  34816u      // vT [64 d][64 c] pitch 144 = 9216
#define CO_SC  44032u      // masked scores [64 c][64 m] pitch 144 = 9216
#define CO_SMEM 53248u

__global__ __launch_bounds__(256, 2)
void chunk_out_kernel(const __half* __restrict__ qfh,
                      const __half* __restrict__ kfh,
                      const __half* __restrict__ vh,
                      const __half* __restrict__ ST,
                      __half* __restrict__ oh)
{
    extern __shared__ __align__(16) char smem[];
    const uint32_t sb = smem_u32(smem);
    const int blk = blockIdx.x;
    const int n = blk & 31, bh = blk >> 5;
    const int b = bh >> 4, h = bh & 15;
    const int tid = threadIdx.x, wid = tid >> 5, lane = tid & 31;

    {
        const int c = tid >> 2, fg = (tid & 3) * 32;
        const size_t src = ((size_t)bh*T_ + n*C_ + c)*F_ + fg;
        uint4* dq = (uint4*)(smem + CO_Q + c*272 + fg*2);
        uint4* dk = (uint4*)(smem + CO_K + c*272 + fg*2);
        #pragma unroll
        for (int q = 0; q < 4; q++) {
            dq[q] = *(const uint4*)(qfh + src + q*8);
            dk[q] = *(const uint4*)(kfh + src + q*8);
        }
    }
    {
        const int c = tid >> 2, dg = (tid & 3) * 16;
        const size_t src = ((size_t)(b*T_) + n*C_ + c)*D_ + h*HD_ + dg;
        union { uint4 u; __half bb[8]; } r;
        #pragma unroll
        for (int q = 0; q < 2; q++) {
            r.u = *(const uint4*)(vh + src + q*8);
            #pragma unroll
            for (int i = 0; i < 8; i++)
                *(__half*)(smem + CO_VT + (dg+q*8+i)*144 + c*2) = r.bb[i];
        }
    }
    __syncthreads();

    const int wm = wid & 3, wn = wid >> 2;
    const int g = lane >> 2, tq = lane & 3;

    const uint32_t aQ = sb + CO_Q + (uint32_t)(wm*16 + (lane & 15))*272 + (uint32_t)(lane >> 4)*16;
    const uint32_t bK = sb + CO_K + (uint32_t)(wn*32 + ((lane >> 4) & 1)*8 + (lane & 7))*272
                      + (uint32_t)((lane >> 3) & 1)*16;

    // ---- scores = q @ k^T ----
    float sacc[4][4];
    #pragma unroll
    for (int i = 0; i < 4; i++)
        #pragma unroll
        for (int j = 0; j < 4; j++) sacc[i][j] = 0.f;

    #pragma unroll
    for (int ks = 0; ks < 8; ks++) {
        const uint32_t koff = (uint32_t)ks*32;
        uint32_t ah[4];
        ldm_x4(aQ + koff, ah[0], ah[1], ah[2], ah[3]);
        uint32_t bw[2][4];
        #pragma unroll
        for (int p = 0; p < 2; p++) {
            const uint32_t ba = bK + (uint32_t)p*16*272 + koff;
            ldm_x4(ba, bw[p][0], bw[p][1], bw[p][2], bw[p][3]);
        }
        #pragma unroll
        for (int nt = 0; nt < 4; nt++) {
            const uint32_t* bp = &bw[nt >> 1][(nt & 1)*2];
            float* d = sacc[nt];
            mma16816h(d[0], d[1], d[2], d[3], ah[0], ah[1], ah[2], ah[3], bp[0], bp[1]);
        }
    }
    #pragma unroll
    for (int nt = 0; nt < 4; nt++) {
        const int colb = wn*32 + nt*8 + tq*2;
        const int r0 = wm*16 + g, r1 = r0 + 8;
        float v00 = (colb     <= r0) ? sacc[nt][0] : 0.f;
        float v01 = (colb + 1 <= r0) ? sacc[nt][1] : 0.f;
        float v10 = (colb     <= r1) ? sacc[nt][2] : 0.f;
        float v11 = (colb + 1 <= r1) ? sacc[nt][3] : 0.f;
        *(__half2*)(smem + CO_SC + r0*144 + colb*2) =
            __halves2half2(__float2half_rn(v00), __float2half_rn(v01));
        *(__half2*)(smem + CO_SC + r1*144 + colb*2) =
            __halves2half2(__float2half_rn(v10), __float2half_rn(v11));
    }
    __syncthreads();

    {
        const int d = tid >> 2, fg = (tid & 3) * 32;
        const size_t src = (size_t)blk*(F_*HD_) + d*F_ + fg;
        uint4* dh = (uint4*)(smem + CO_K + d*272 + fg*2);
        #pragma unroll
        for (int q = 0; q < 4; q++)
            dh[q] = *(const uint4*)(ST + src + q*8);
    }
    __syncthreads();

    // ---- out = q @ S_excl + scores @ v ----
    float oacc[4][4];
    #pragma unroll
    for (int i = 0; i < 4; i++)
        #pragma unroll
        for (int j = 0; j < 4; j++) oacc[i][j] = 0.f;

    #pragma unroll
    for (int ks = 0; ks < 8; ks++) {     // inter
        const uint32_t koff = (uint32_t)ks*32;
        uint32_t ah[4];
        ldm_x4(aQ + koff, ah[0], ah[1], ah[2], ah[3]);
        uint32_t bw[2][4];
        #pragma unroll
        for (int p = 0; p < 2; p++) {
            const uint32_t ba = bK + (uint32_t)p*16*272 + koff;
            ldm_x4(ba, bw[p][0], bw[p][1], bw[p][2], bw[p][3]);
        }
        #pragma unroll
        for (int nt = 0; nt < 4; nt++) {
            const uint32_t* bp = &bw[nt >> 1][(nt & 1)*2];
            float* d = oacc[nt];
            mma16816h(d[0], d[1], d[2], d[3], ah[0], ah[1], ah[2], ah[3], bp[0], bp[1]);
        }
    }
    {   // intra
        const uint32_t aS = sb + CO_SC + (uint32_t)(wm*16 + (lane & 15))*144
                          + (uint32_t)(lane >> 4)*16;
        const uint32_t bV = sb + CO_VT + (uint32_t)(wn*32 + ((lane >> 4) & 1)*8 + (lane & 7))*144
                          + (uint32_t)((lane >> 3) & 1)*16;
        #pragma unroll
        for (int ks = 0; ks < 4; ks++) {
            const uint32_t koff = (uint32_t)ks*32;
            uint32_t ah[4];
            ldm_x4(aS + koff, ah[0], ah[1], ah[2], ah[3]);
            uint32_t bw[2][4];
            #pragma unroll
            for (int p = 0; p < 2; p++) {
                const uint32_t ba = bV + (uint32_t)p*16*144 + koff;
                ldm_x4(ba, bw[p][0], bw[p][1], bw[p][2], bw[p][3]);
            }
            #pragma unroll
            for (int nt = 0; nt < 4; nt++) {
                const uint32_t* bp = &bw[nt >> 1][(nt & 1)*2];
                float* d = oacc[nt];
                mma16816h(d[0], d[1], d[2], d[3], ah[0], ah[1], ah[2], ah[3], bp[0], bp[1]);
            }
        }
    }

    // write o single fp16 in [B,T,H*HD] layout
    #pragma unroll
    for (int nt = 0; nt < 4; nt++) {
        const int dcol = wn*32 + nt*8 + tq*2;
        const int r0 = wm*16 + g;
        #pragma unroll
        for (int half = 0; half < 2; half++) {
            const int r = r0 + half*8;
            const size_t oidx = ((size_t)(b*T_) + n*C_ + r)*D_ + h*HD_ + dcol;
            *(__half2*)(oh + oidx) =
                __halves2half2(__float2half_rn(oacc[nt][half*2]),
                               __float2half_rn(oacc[nt][half*2+1]));
        }
    }
}

// ---------------- launcher ----------------------------------------------------
extern "C" void kernel_launch(void* const* d_in, const int* in_sizes, int n_in,
                              void* d_out, int out_size)
{
    const float* hs   = (const float*)d_in[0];
    const float* res  = (const float*)d_in[1];
    const float* nw   = (const float*)d_in[2];
    const float* w_q  = (const float*)d_in[3];
    const float* w_k  = (const float*)d_in[4];
    const float* w_v  = (const float*)d_in[5];
    const float* w_o  = (const float*)d_in[6];
    const float* hqw  = (const float*)d_in[7];
    const float* hqb  = (const float*)d_in[8];
    const float* hkw  = (const float*)d_in[9];
    const float* hkb  = (const float*)d_in[10];
    float* out = (float*)d_out;

    __half *pkv, *pxh, *poh, *pwT, *pwo, *pqfh, *pkfh, *pvh, *pST;
    cudaGetSymbolAddress((void**)&pkv,  g_kv);
    cudaGetSymbolAddress((void**)&pxh,  g_xh);
    cudaGetSymbolAddress((void**)&poh,  g_oh);
    cudaGetSymbolAddress((void**)&pwT,  g_wT);
    cudaGetSymbolAddress((void**)&pwo,  g_woT);
    cudaGetSymbolAddress((void**)&pqfh, g_qfh);
    cudaGetSymbolAddress((void**)&pkfh, g_kfh);
    cudaGetSymbolAddress((void**)&pvh,  g_vh);
    cudaGetSymbolAddress((void**)&pST,  g_ST);

    const int fsmem = (128*65 + 64*64) * sizeof(float);   // 49664
    cudaFuncSetAttribute(weightprep_kernel,
                         cudaFuncAttributeMaxDynamicSharedMemorySize, fsmem);
    cudaFuncSetAttribute(gemm_qkv,
                         cudaFuncAttributeMaxDynamicSharedMemorySize, GSMEM);
    cudaFuncSetAttribute(gemm_o,
                         cudaFuncAttributeMaxDynamicSharedMemorySize, GSMEM);
    cudaFuncSetAttribute(chunk_kv_kernel,
                         cudaFuncAttributeMaxDynamicSharedMemorySize, CKV_SMEM);
    cudaFuncSetAttribute(chunk_out_kernel,
                         cudaFuncAttributeMaxDynamicSharedMemorySize, CO_SMEM);

    // 1) weight prep (fold hedgehog into q/k; transpose v, o) -> fp16
    weightprep_kernel<<<dim3(16, 8, 4), 256, fsmem>>>(w_q, w_k, w_v, w_o, hqw, hkw, pwT, pwo);

    // 2+3) fused add + RMSNorm (two halves -> keeps gemm_qkv as launch #4)
    addnorm_kernel<<<BT_/2, 256>>>(hs, res, nw, out + (size_t)BT_*D_, pxh, 0);
    addnorm_kernel<<<BT_/2, 256>>>(hs, res, nw, out + (size_t)BT_*D_, pxh, BT_/2);

    // 4) fused QKV projection + hedgehog epilogue (KT=32, 4-stage)
    dim3 qkvgrid(24, BT_/128);
    gemm_qkv<<<qkvgrid, 256, GSMEM>>>(pxh, pwT, hqb, hkb, pqfh, pkfh, pvh);

    // 5) chunked linear attention (single fp16 tensor cores)
    chunk_kv_kernel<<<NCHUNK_, 256, CKV_SMEM>>>(pkfh, pvh, pkv);
    kv_scan_kernel<<<512, 1024>>>(pkv, pST);
    chunk_out_kernel<<<NCHUNK_, 256, CO_SMEM>>>(pqfh, pkfh, pvh, pST, poh);

    // 6) output projection (KT=32, 4-stage)
    gemm_o<<<dim3(8, BT_/128), 256, GSMEM>>>(poh, pwo, out);
}

// round 14
// speedup vs baseline: 1.0657x; 1.0049x over previous
#include <cuda_runtime.h>
#include <cuda_bf16.h>
#include <cuda_fp16.h>
#include <stdint.h>
#include <math.h>

// Problem constants
#define B_  4
#define T_  2048
#define D_  1024
#define H_  16
#define HD_ 64
#define F_  128
#define C_  64
#define N_  32
#define BT_ (B_*T_)        // 8192
#define BHT_ (B_*H_*T_)    // 131072
#define NCHUNK_ (B_*H_*N_) // 2048

// ---------------- scratch (device globals) ----------------------------------
__device__ __half g_kv [NCHUNK_*F_*HD_];        // kv^T per chunk (fp16)
__device__ __half g_ST [NCHUNK_*F_*HD_];        // S_excl^T single fp16
__device__ __half g_qfh[BHT_*F_];               // q features single fp16
__device__ __half g_kfh[BHT_*F_];               // k features single fp16
__device__ __half g_vh [BT_*D_];                // v single fp16
__device__ __half g_xh [BT_*D_];                // x single fp16
__device__ __half g_oh [BT_*D_];                // attention out single fp16
__device__ __half g_wT [3*D_*D_];               // fused qkv weights, fp16 single
__device__ __half g_woT[D_*D_];                 // o weights, fp16 single

// ---------------- PTX helpers ------------------------------------------------
__device__ __forceinline__ uint32_t smem_u32(const void* p) {
    uint32_t a;
    asm("{ .reg .u64 t; cvta.to.shared.u64 t, %1; cvt.u32.u64 %0, t; }" : "=r"(a) : "l"(p));
    return a;
}
__device__ __forceinline__ void cp_async16(uint32_t saddr, const void* gaddr) {
    asm volatile("cp.async.cg.shared.global [%0], [%1], 16;" :: "r"(saddr), "l"(gaddr));
}
__device__ __forceinline__ void cp_commit() {
    asm volatile("cp.async.commit_group;" ::: "memory");
}
template <int NN>
__device__ __forceinline__ void cp_wait() {
    asm volatile("cp.async.wait_group %0;" :: "n"(NN) : "memory");
}
__device__ __forceinline__ void ldm_x4(uint32_t addr, uint32_t& r0, uint32_t& r1,
                                       uint32_t& r2, uint32_t& r3) {
    asm volatile("ldmatrix.sync.aligned.m8n8.x4.shared.b16 {%0,%1,%2,%3}, [%4];"
                 : "=r"(r0), "=r"(r1), "=r"(r2), "=r"(r3) : "r"(addr));
}
__device__ __forceinline__ void mma16816h(float& d0, float& d1, float& d2, float& d3,
                                          uint32_t a0, uint32_t a1, uint32_t a2, uint32_t a3,
                                          uint32_t b0, uint32_t b1) {
    asm volatile("mma.sync.aligned.m16n8k16.row.col.f32.f16.f16.f32 "
                 "{%0,%1,%2,%3}, {%4,%5,%6,%7}, {%8,%9}, {%0,%1,%2,%3};"
                 : "+f"(d0), "+f"(d1), "+f"(d2), "+f"(d3)
                 : "r"(a0), "r"(a1), "r"(a2), "r"(a3), "r"(b0), "r"(b1));
}

// ---------------- weight prep: fold/transpose -> fp16, z-dispatched ----------
__global__ __launch_bounds__(256)
void weightprep_kernel(const float* __restrict__ wq, const float* __restrict__ wk,
                       const float* __restrict__ wv, const float* __restrict__ wo,
                       const float* __restrict__ hqw, const float* __restrict__ hkw,
                       __half* __restrict__ wT, __half* __restrict__ woT)
{
    extern __shared__ float fsm[];
    float* Wb = fsm;               // [128][65]
    float* hh = fsm + 128*65;      // [64][64]
    const int z = blockIdx.z;
    const float* W   = (z==0) ? wq : (z==1) ? wk : (z==2) ? wv : wo;
    const float* hhw = (z==0) ? hqw : (z==1) ? hkw : nullptr;
    __half* dst = (z==3) ? woT : wT;
    const int rowOff = (z==0) ? 0 : (z==1) ? 1024 : (z==2) ? 2048 : 0;

    const int h = blockIdx.x, kb = blockIdx.y;
    const int tid = threadIdx.x;
    for (int i = tid; i < 8192; i += 256) {
        int r = i >> 6, d = i & 63;
        Wb[r*65 + d] = W[(size_t)(kb*128 + r)*D_ + h*64 + d];
    }
    if (hhw)
        for (int i = tid; i < 4096; i += 256) hh[i] = hhw[i];
    __syncthreads();

    const int kk = tid & 127;
    const int e0 = (tid >> 7) * 32;
    float acc[32];
    if (hhw) {
        #pragma unroll
        for (int e = 0; e < 32; e++) acc[e] = 0.f;
        for (int d = 0; d < 64; d++) {
            float wv2 = Wb[kk*65 + d];
            #pragma unroll
            for (int e = 0; e < 32; e++)
                acc[e] = fmaf(wv2, hh[(e0+e)*64 + d], acc[e]);
        }
    } else {
        #pragma unroll
        for (int e = 0; e < 32; e++) acc[e] = Wb[kk*65 + e0 + e];
    }
    #pragma unroll
    for (int e = 0; e < 32; e++) {
        size_t idx = (size_t)(rowOff + h*64 + e0 + e)*D_ + kb*128 + kk;
        dst[idx] = __float2half_rn(acc[e]);
    }
}

// ---------------- fused add + RMSNorm -> resid + fp16 x ----------------------
__global__ __launch_bounds__(256)
void addnorm_kernel(const float* __restrict__ hs, const float* __restrict__ res,
                    const float* __restrict__ w, float* __restrict__ resid_out,
                    __half* __restrict__ xh)
{
    __shared__ float red[8];
    const int row = blockIdx.x;
    const int t = threadIdx.x;
    const float4* h4 = (const float4*)(hs  + (size_t)row*D_);
    const float4* r4 = (const float4*)(res + (size_t)row*D_);
    float4*      ro4 = (float4*)(resid_out + (size_t)row*D_);

    float4 h = h4[t], r = r4[t];
    float4 s = make_float4(h.x+r.x, h.y+r.y, h.z+r.z, h.w+r.w);
    ro4[t] = s;
    float ss = s.x*s.x + s.y*s.y + s.z*s.z + s.w*s.w;
    #pragma unroll
    for (int o = 16; o; o >>= 1) ss += __shfl_xor_sync(0xffffffffu, ss, o);
    if ((t & 31) == 0) red[t >> 5] = ss;
    __syncthreads();
    float tot = 0.f;
    #pragma unroll
    for (int i = 0; i < 8; i++) tot += red[i];
    float rstd = rsqrtf(tot * (1.0f/1024.0f) + 1e-5f);
    float4 wv = ((const float4*)w)[t];
    size_t idx = (size_t)row*D_ + t*4;
    *(__half2*)(xh+idx)   = __halves2half2(__float2half_rn(s.x*rstd*wv.x),
                                           __float2half_rn(s.y*rstd*wv.y));
    *(__half2*)(xh+idx+2) = __halves2half2(__float2half_rn(s.z*rstd*wv.z),
                                           __float2half_rn(s.w*rstd*wv.w));
}

// ---------------- fp16 fused QKV GEMM + hedgehog epilogue ---------------------
// Single fp16 A and W. K-tile 32, pitch 80, 4-stage pipeline, cp_wait<2>.
#define PITCH 40
#define MAT_BYTES (128*PITCH*2)          // 10240
#define STAGEB (2*MAT_BYTES)             // 20480
#define GSMEM (4*STAGEB)                 // 81920

__global__ __launch_bounds__(256, 2)
void gemm_qkv(const __half* __restrict__ Ah, const __half* __restrict__ W,
              const float* __restrict__ biasq, const float* __restrict__ biask,
              __half* __restrict__ Qfh, __half* __restrict__ Kfh,
              __half* __restrict__ Vh)
{
    extern __shared__ __align__(16) char smem[];
    const uint32_t sbase = smem_u32(smem);
    const int tid = threadIdx.x, wid = tid >> 5, lane = tid & 31;
    const int bx = blockIdx.x, by = blockIdx.y;
    const int wm = wid & 1, wn = wid >> 1;

    const int lrow = tid >> 1;
    const int lc   = (tid & 1) * 2;
    const size_t gA = (size_t)(by*128 + lrow) * D_;
    const size_t gB = (size_t)(bx*128 + lrow) * D_;
    const uint32_t sRow = (uint32_t)lrow * 80;

    float acc[4][4][4];
    #pragma unroll
    for (int i = 0; i < 4; i++)
        #pragma unroll
        for (int j = 0; j < 4; j++)
            #pragma unroll
            for (int l = 0; l < 4; l++) acc[i][j][l] = 0.f;

    #define PREFETCH(kt, buf) do {                                              \
        const int k0 = (kt) * 32;                                               \
        const uint32_t b0 = sbase + (uint32_t)(buf) * STAGEB;                   \
        _Pragma("unroll")                                                       \
        for (int u = 0; u < 2; u++) {                                           \
            const int c = lc + u;                                               \
            const uint32_t so = sRow + (uint32_t)c * 16;                        \
            const size_t go = (size_t)k0 + c * 8;                               \
            cp_async16(b0 + 0*MAT_BYTES + so, Ah + gA + go);                    \
            cp_async16(b0 + 1*MAT_BYTES + so, W  + gB + go);                    \
        }                                                                       \
        cp_commit();                                                            \
    } while (0)

    PREFETCH(0, 0);
    PREFETCH(1, 1);
    PREFETCH(2, 2);

    const uint32_t aRow = (uint32_t)(wm*64 + (lane & 15)) * 80 + (uint32_t)(lane >> 4) * 16;
    const uint32_t bRow = (uint32_t)(wn*32 + ((lane >> 4) & 1)*8 + (lane & 7)) * 80
                        + (uint32_t)((lane >> 3) & 1) * 16;

    const int TILES = D_ / 32;   // 32
    int buf = 0;                 // kt % 4
    #pragma unroll 1
    for (int kt = 0; kt < TILES; kt++) {
        if (kt >= TILES - 3) cp_wait<0>(); else cp_wait<2>();
        __syncthreads();
        if (kt + 3 < TILES) {
            int b3 = buf + 3; if (b3 >= 4) b3 -= 4;
            PREFETCH(kt + 3, b3);
        }
        const uint32_t sb = sbase + (uint32_t)buf * STAGEB;

        #pragma unroll
        for (int kk = 0; kk < 2; kk++) {
            const uint32_t koff = (uint32_t)kk * 32;
            uint32_t bw[2][4];
            #pragma unroll
            for (int nt2 = 0; nt2 < 2; nt2++) {
                const uint32_t ba = bRow + (uint32_t)nt2 * 16 * 80 + koff;
                ldm_x4(sb + 1*MAT_BYTES + ba, bw[nt2][0], bw[nt2][1], bw[nt2][2], bw[nt2][3]);
            }
            #pragma unroll
            for (int mt = 0; mt < 4; mt++) {
                const uint32_t aa = aRow + (uint32_t)mt * 16 * 80 + koff;
                uint32_t ah[4];
                ldm_x4(sb + aa, ah[0], ah[1], ah[2], ah[3]);
                #pragma unroll
                for (int nt = 0; nt < 4; nt++) {
                    const uint32_t* bp = &bw[nt >> 1][(nt & 1) * 2];
                    float* d = acc[mt][nt];
                    mma16816h(d[0], d[1], d[2], d[3], ah[0], ah[1], ah[2], ah[3], bp[0], bp[1]);
                }
            }
        }
        buf++; if (buf == 4) buf = 0;
    }
    #undef PREFETCH
    __syncthreads();    // smem reuse below

    const int g = lane >> 2, tq = lane & 3;

    if (bx < 16) {
        // -------- hedgehog epilogue: bias + softmax([y,-y]) -> fp16 ----------
        const int isQ = (bx < 8);
        const float* bias = isQ ? biasq : biask;
        const float scale = isQ ? 0.08838834764831845f : 1.0f;
        __half* fh = isQ ? Qfh : Kfh;
        float* smax = (float*)smem;          // [4][128]
        float* ssum = smax + 512;            // [4][128]
        #pragma unroll
        for (int mt = 0; mt < 4; mt++) {
            float pm0 = 0.f, pm1 = 0.f;
            #pragma unroll
            for (int nt = 0; nt < 4; nt++) {
                const int cb = (wn*32 + nt*8 + tq*2) & 63;
                const float b0 = bias[cb], b1 = bias[cb + 1];
                float* d = acc[mt][nt];
                d[0] += b0; d[1] += b1; d[2] += b0; d[3] += b1;
                pm0 = fmaxf(pm0, fmaxf(fabsf(d[0]), fabsf(d[1])));
                pm1 = fmaxf(pm1, fmaxf(fabsf(d[2]), fabsf(d[3])));
            }
            pm0 = fmaxf(pm0, __shfl_xor_sync(0xffffffffu, pm0, 1));
            pm0 = fmaxf(pm0, __shfl_xor_sync(0xffffffffu, pm0, 2));
            pm1 = fmaxf(pm1, __shfl_xor_sync(0xffffffffu, pm1, 1));
            pm1 = fmaxf(pm1, __shfl_xor_sync(0xffffffffu, pm1, 2));
            if (tq == 0) {
                smax[wn*128 + wm*64 + mt*16 + g]     = pm0;
                smax[wn*128 + wm*64 + mt*16 + g + 8] = pm1;
            }
        }
        __syncthreads();
        float mrow[4][2];
        #pragma unroll
        for (int mt = 0; mt < 4; mt++) {
            #pragma unroll
            for (int half = 0; half < 2; half++) {
                const int r = wm*64 + mt*16 + g + half*8;
                mrow[mt][half] = fmaxf(smax[wn*128 + r], smax[(wn^1)*128 + r]);
            }
        }
        #pragma unroll
        for (int mt = 0; mt < 4; mt++) {
            float s0 = 0.f, s1 = 0.f;
            #pragma unroll
            for (int nt = 0; nt < 4; nt++) {
                const float* d = acc[mt][nt];
                s0 += __expf(d[0]-mrow[mt][0]) + __expf(-d[0]-mrow[mt][0])
                    + __expf(d[1]-mrow[mt][0]) + __expf(-d[1]-mrow[mt][0]);
                s1 += __expf(d[2]-mrow[mt][1]) + __expf(-d[2]-mrow[mt][1])
                    + __expf(d[3]-mrow[mt][1]) + __expf(-d[3]-mrow[mt][1]);
            }
            s0 += __shfl_xor_sync(0xffffffffu, s0, 1);
            s0 += __shfl_xor_sync(0xffffffffu, s0, 2);
            s1 += __shfl_xor_sync(0xffffffffu, s1, 1);
            s1 += __shfl_xor_sync(0xffffffffu, s1, 2);
            if (tq == 0) {
                ssum[wn*128 + wm*64 + mt*16 + g]     = s0;
                ssum[wn*128 + wm*64 + mt*16 + g + 8] = s1;
            }
        }
        __syncthreads();
        const int hloc = (bx & 7)*2 + (wn >> 1);
        #pragma unroll
        for (int mt = 0; mt < 4; mt++) {
            #pragma unroll
            for (int half = 0; half < 2; half++) {
                const int r = wm*64 + mt*16 + g + half*8;
                const float z = ssum[wn*128 + r] + ssum[(wn^1)*128 + r];
                const float inv = scale / z;
                const float mm = mrow[mt][half];
                const int rowg = by*128 + r;
                const int bb = rowg >> 11, tt = rowg & 2047;
                const size_t base = ((size_t)(bb*H_ + hloc)*T_ + tt)*F_;
                #pragma unroll
                for (int nt = 0; nt < 4; nt++) {
                    const int f = (wn*32 + nt*8 + tq*2) & 63;
                    const float y0 = acc[mt][nt][half*2], y1 = acc[mt][nt][half*2+1];
                    const float p0 = __expf(y0 - mm)*inv,  p1 = __expf(y1 - mm)*inv;
                    const float n0 = __expf(-y0 - mm)*inv, n1 = __expf(-y1 - mm)*inv;
                    *(__half2*)(fh + base + f) =
                        __halves2half2(__float2half_rn(p0), __float2half_rn(p1));
                    *(__half2*)(fh + base + 64 + f) =
                        __halves2half2(__float2half_rn(n0), __float2half_rn(n1));
                }
            }
        }
    } else {
        // -------- v epilogue: single fp16 ----
        const int colbase = (bx - 16)*128;
        #pragma unroll
        for (int mt = 0; mt < 4; mt++) {
            const int r0 = by*128 + wm*64 + mt*16 + g;
            #pragma unroll
            for (int nt = 0; nt < 4; nt++) {
                const int col = colbase + wn*32 + nt*8 + tq*2;
                float* d = acc[mt][nt];
                *(__half2*)(Vh + (size_t)r0*D_ + col) =
                    __halves2half2(__float2half_rn(d[0]), __float2half_rn(d[1]));
                *(__half2*)(Vh + (size_t)(r0+8)*D_ + col) =
                    __halves2half2(__float2half_rn(d[2]), __float2half_rn(d[3]));
            }
        }
    }
}

// ---------------- fp16 GEMM (fp32 out; o-projection) --------------------------
__global__ __launch_bounds__(256, 2)
void gemm_o(const __half* __restrict__ Ah, const __half* __restrict__ W,
            float* __restrict__ Cout)
{
    extern __shared__ __align__(16) char smem[];
    const uint32_t sbase = smem_u32(smem);
    const int tid = threadIdx.x, wid = tid >> 5, lane = tid & 31;
    const int bx = blockIdx.x, by = blockIdx.y;
    const int wm = wid & 1, wn = wid >> 1;

    const int lrow = tid >> 1;
    const int lc   = (tid & 1) * 2;
    const size_t gA = (size_t)(by*128 + lrow) * D_;
    const size_t gB = (size_t)(bx*128 + lrow) * D_;
    const uint32_t sRow = (uint32_t)lrow * 80;

    float acc[4][4][4];
    #pragma unroll
    for (int i = 0; i < 4; i++)
        #pragma unroll
        for (int j = 0; j < 4; j++)
            #pragma unroll
            for (int l = 0; l < 4; l++) acc[i][j][l] = 0.f;

    #define PREFETCH(kt, buf) do {                                              \
        const int k0 = (kt) * 32;                                               \
        const uint32_t b0 = sbase + (uint32_t)(buf) * STAGEB;                   \
        _Pragma("unroll")                                                       \
        for (int u = 0; u < 2; u++) {                                           \
            const int c = lc + u;                                               \
            const uint32_t so = sRow + (uint32_t)c * 16;                        \
            const size_t go = (size_t)k0 + c * 8;                               \
            cp_async16(b0 + 0*MAT_BYTES + so, Ah + gA + go);                    \
            cp_async16(b0 + 1*MAT_BYTES + so, W  + gB + go);                    \
        }                                                                       \
        cp_commit();                                                            \
    } while (0)

    PREFETCH(0, 0);
    PREFETCH(1, 1);
    PREFETCH(2, 2);

    const uint32_t aRow = (uint32_t)(wm*64 + (lane & 15)) * 80 + (uint32_t)(lane >> 4) * 16;
    const uint32_t bRow = (uint32_t)(wn*32 + ((lane >> 4) & 1)*8 + (lane & 7)) * 80
                        + (uint32_t)((lane >> 3) & 1) * 16;

    const int TILES = D_ / 32;
    int buf = 0;
    #pragma unroll 1
    for (int kt = 0; kt < TILES; kt++) {
        if (kt >= TILES - 3) cp_wait<0>(); else cp_wait<2>();
        __syncthreads();
        if (kt + 3 < TILES) {
            int b3 = buf + 3; if (b3 >= 4) b3 -= 4;
            PREFETCH(kt + 3, b3);
        }
        const uint32_t sb = sbase + (uint32_t)buf * STAGEB;

        #pragma unroll
        for (int kk = 0; kk < 2; kk++) {
            const uint32_t koff = (uint32_t)kk * 32;
            uint32_t bw[2][4];
            #pragma unroll
            for (int nt2 = 0; nt2 < 2; nt2++) {
                const uint32_t ba = bRow + (uint32_t)nt2 * 16 * 80 + koff;
                ldm_x4(sb + 1*MAT_BYTES + ba, bw[nt2][0], bw[nt2][1], bw[nt2][2], bw[nt2][3]);
            }
            #pragma unroll
            for (int mt = 0; mt < 4; mt++) {
                const uint32_t aa = aRow + (uint32_t)mt * 16 * 80 + koff;
                uint32_t ah[4];
                ldm_x4(sb + aa, ah[0], ah[1], ah[2], ah[3]);
                #pragma unroll
                for (int nt = 0; nt < 4; nt++) {
                    const uint32_t* bp = &bw[nt >> 1][(nt & 1) * 2];
                    float* d = acc[mt][nt];
                    mma16816h(d[0], d[1], d[2], d[3], ah[0], ah[1], ah[2], ah[3], bp[0], bp[1]);
                }
            }
        }
        buf++; if (buf == 4) buf = 0;
    }
    #undef PREFETCH

    const int g = lane >> 2, tq = lane & 3;
    #pragma unroll
    for (int mt = 0; mt < 4; mt++) {
        const int r0 = by*128 + wm*64 + mt*16 + g;
        #pragma unroll
        for (int nt = 0; nt < 4; nt++) {
            const int col = bx*128 + wn*32 + nt*8 + tq*2;
            float* d = acc[mt][nt];
            *(float2*)(Cout + (size_t)r0*D_ + col)     = make_float2(d[0], d[1]);
            *(float2*)(Cout + (size_t)(r0+8)*D_ + col) = make_float2(d[2], d[3]);
        }
    }
}

// ---------------- phase A: kv^T[d][f] = sum_c v[c,d] k[c,f]  (single fp16) ---
#define CKV_KT  0u                         // [128 f][64 c] pitch 144 = 18432
#define CKV_VT  18432u                     // [64 d][64 c] pitch 144 = 9216
#define CKV_SMEM 27648u

__global__ __launch_bounds__(256, 3)
void chunk_kv_kernel(const __half* __restrict__ kfh,
                     const __half* __restrict__ vh,
                     __half* __restrict__ kvT)
{
    extern __shared__ __align__(16) char smem[];
    const uint32_t sb = smem_u32(smem);
    const int blk = blockIdx.x;
    const int n = blk & 31, bh = blk >> 5;
    const int b = bh >> 4, h = bh & 15;
    const int tid = threadIdx.x, wid = tid >> 5, lane = tid & 31;

    {
        const int c = tid >> 2, fg = (tid & 3) * 32;
        const size_t src = ((size_t)bh*T_ + n*C_ + c)*F_ + fg;
        union { uint4 u; __half b[8]; } r;
        #pragma unroll
        for (int q = 0; q < 4; q++) {
            r.u = *(const uint4*)(kfh + src + q*8);
            #pragma unroll
            for (int i = 0; i < 8; i++)
                *(__half*)(smem + CKV_KT + (fg+q*8+i)*144 + c*2) = r.b[i];
        }
    }
    {
        const int c = tid >> 2, dg = (tid & 3) * 16;
        const size_t src = ((size_t)(b*T_) + n*C_ + c)*D_ + h*HD_ + dg;
        union { uint4 u; __half b[8]; } r;
        #pragma unroll
        for (int q = 0; q < 2; q++) {
            r.u = *(const uint4*)(vh + src + q*8);
            #pragma unroll
            for (int i = 0; i < 8; i++)
                *(__half*)(smem + CKV_VT + (dg+q*8+i)*144 + c*2) = r.b[i];
        }
    }
    __syncthreads();

    const int wm = wid & 3, wn = wid >> 2;
    float acc[8][4];
    #pragma unroll
    for (int i = 0; i < 8; i++)
        #pragma unroll
        for (int j = 0; j < 4; j++) acc[i][j] = 0.f;

    const uint32_t aBase = sb + CKV_VT + (uint32_t)(wm*16 + (lane & 15))*144
                         + (uint32_t)(lane >> 4)*16;
    const uint32_t bBase = sb + CKV_KT + (uint32_t)(wn*64 + ((lane >> 4) & 1)*8 + (lane & 7))*144
                         + (uint32_t)((lane >> 3) & 1)*16;

    #pragma unroll
    for (int ks = 0; ks < 4; ks++) {
        const uint32_t koff = (uint32_t)ks*32;
        uint32_t ah[4];
        ldm_x4(aBase + koff, ah[0], ah[1], ah[2], ah[3]);
        uint32_t bw[4][4];
        #pragma unroll
        for (int p = 0; p < 4; p++) {
            const uint32_t ba = bBase + (uint32_t)p*16*144 + koff;
            ldm_x4(ba, bw[p][0], bw[p][1], bw[p][2], bw[p][3]);
        }
        #pragma unroll
        for (int nt = 0; nt < 8; nt++) {
            const uint32_t* bp = &bw[nt >> 1][(nt & 1)*2];
            float* d = acc[nt];
            mma16816h(d[0], d[1], d[2], d[3], ah[0], ah[1], ah[2], ah[3], bp[0], bp[1]);
        }
    }
    const int g = lane >> 2, tq = lane & 3;
    __half* out = kvT + (size_t)blk * (F_*HD_);
    #pragma unroll
    for (int nt = 0; nt < 8; nt++) {
        const int f = wn*64 + nt*8 + tq*2;
        const int d0 = wm*16 + g;
        *(__half2*)(out + (size_t)d0*F_ + f) =
            __halves2half2(__float2half_rn(acc[nt][0]), __float2half_rn(acc[nt][1]));
        *(__half2*)(out + (size_t)(d0+8)*F_ + f) =
            __halves2half2(__float2half_rn(acc[nt][2]), __float2half_rn(acc[nt][3]));
    }
}

// ---------------- phase B: exclusive cumsum (fp32 acc) -> single fp16 --------
__global__ __launch_bounds__(1024)
void kv_scan_kernel(const __half* __restrict__ kvT, __half* __restrict__ ST)
{
    const int blk = blockIdx.x;
    const int bh = blk >> 3, seg = blk & 7;
    const int e = seg*1024 + threadIdx.x;
    size_t base = (size_t)bh * N_ * (F_*HD_) + e;
    float acc = 0.f;
    for (int n = 0; n < N_; n++) {
        size_t idx = base + (size_t)n * (F_*HD_);
        ST[idx] = __float2half_rn(acc);
        acc += __half2float(kvT[idx]);
    }
}

// ---------------- phase C: out = q@S_excl + tril(q@k^T)@v  (single fp16) -----
#define CO_Q   0u          // [64 c][128 f] pitch 272 = 17408
#define CO_K   17408u      // k [c][f]; later ST [d][f]
#define CO_VT  34816u      // vT [64 d][64 c] pitch 144 = 9216
#define CO_SC  44032u      // masked scores [64 c][64 m] pitch 144 = 9216
#define CO_SMEM 53248u

__global__ __launch_bounds__(256, 3)
void chunk_out_kernel(const __half* __restrict__ qfh,
                      const __half* __restrict__ kfh,
                      const __half* __restrict__ vh,
                      const __half* __restrict__ ST,
                      __half* __restrict__ oh)
{
    extern __shared__ __align__(16) char smem[];
    const uint32_t sb = smem_u32(smem);
    const int blk = blockIdx.x;
    const int n = blk & 31, bh = blk >> 5;
    const int b = bh >> 4, h = bh & 15;
    const int tid = threadIdx.x, wid = tid >> 5, lane = tid & 31;

    {
        const int c = tid >> 2, fg = (tid & 3) * 32;
        const size_t src = ((size_t)bh*T_ + n*C_ + c)*F_ + fg;
        uint4* dq = (uint4*)(smem + CO_Q + c*272 + fg*2);
        uint4* dk = (uint4*)(smem + CO_K + c*272 + fg*2);
        #pragma unroll
        for (int q = 0; q < 4; q++) {
            dq[q] = *(const uint4*)(qfh + src + q*8);
            dk[q] = *(const uint4*)(kfh + src + q*8);
        }
    }
    {
        const int c = tid >> 2, dg = (tid & 3) * 16;
        const size_t src = ((size_t)(b*T_) + n*C_ + c)*D_ + h*HD_ + dg;
        union { uint4 u; __half bb[8]; } r;
        #pragma unroll
        for (int q = 0; q < 2; q++) {
            r.u = *(const uint4*)(vh + src + q*8);
            #pragma unroll
            for (int i = 0; i < 8; i++)
                *(__half*)(smem + CO_VT + (dg+q*8+i)*144 + c*2) = r.bb[i];
        }
    }
    __syncthreads();

    const int wm = wid & 3, wn = wid >> 2;
    const int g = lane >> 2, tq = lane & 3;

    const uint32_t aQ = sb + CO_Q + (uint32_t)(wm*16 + (lane & 15))*272 + (uint32_t)(lane >> 4)*16;
    const uint32_t bK = sb + CO_K + (uint32_t)(wn*32 + ((lane >> 4) & 1)*8 + (lane & 7))*272
                      + (uint32_t)((lane >> 3) & 1)*16;

    // ---- scores = q @ k^T ----
    float sacc[4][4];
    #pragma unroll
    for (int i = 0; i < 4; i++)
        #pragma unroll
        for (int j = 0; j < 4; j++) sacc[i][j] = 0.f;

    #pragma unroll
    for (int ks = 0; ks < 8; ks++) {
        const uint32_t koff = (uint32_t)ks*32;
        uint32_t ah[4];
        ldm_x4(aQ + koff, ah[0], ah[1], ah[2], ah[3]);
        uint32_t bw[2][4];
        #pragma unroll
        for (int p = 0; p < 2; p++) {
            const uint32_t ba = bK + (uint32_t)p*16*272 + koff;
            ldm_x4(ba, bw[p][0], bw[p][1], bw[p][2], bw[p][3]);
        }
        #pragma unroll
        for (int nt = 0; nt < 4; nt++) {
            const uint32_t* bp = &bw[nt >> 1][(nt & 1)*2];
            float* d = sacc[nt];
            mma16816h(d[0], d[1], d[2], d[3], ah[0], ah[1], ah[2], ah[3], bp[0], bp[1]);
        }
    }
    #pragma unroll
    for (int nt = 0; nt < 4; nt++) {
        const int colb = wn*32 + nt*8 + tq*2;
        const int r0 = wm*16 + g, r1 = r0 + 8;
        float v00 = (colb     <= r0) ? sacc[nt][0] : 0.f;
        float v01 = (colb + 1 <= r0) ? sacc[nt][1] : 0.f;
        float v10 = (colb     <= r1) ? sacc[nt][2] : 0.f;
        float v11 = (colb + 1 <= r1) ? sacc[nt][3] : 0.f;
        *(__half2*)(smem + CO_SC + r0*144 + colb*2) =
            __halves2half2(__float2half_rn(v00), __float2half_rn(v01));
        *(__half2*)(smem + CO_SC + r1*144 + colb*2) =
            __halves2half2(__float2half_rn(v10), __float2half_rn(v11));
    }
    __syncthreads();

    {
        const int d = tid >> 2, fg = (tid & 3) * 32;
        const size_t src = (size_t)blk*(F_*HD_) + d*F_ + fg;
        uint4* dh = (uint4*)(smem + CO_K + d*272 + fg*2);
        #pragma unroll
        for (int q = 0; q < 4; q++)
            dh[q] = *(const uint4*)(ST + src + q*8);
    }
    __syncthreads();

    // ---- out = q @ S_excl + scores @ v ----
    float oacc[4][4];
    #pragma unroll
    for (int i = 0; i < 4; i++)
        #pragma unroll
        for (int j = 0; j < 4; j++) oacc[i][j] = 0.f;

    #pragma unroll
    for (int ks = 0; ks < 8; ks++) {     // inter
        const uint32_t koff = (uint32_t)ks*32;
        uint32_t ah[4];
        ldm_x4(aQ + koff, ah[0], ah[1], ah[2], ah[3]);
        uint32_t bw[2][4];
        #pragma unroll
        for (int p = 0; p < 2; p++) {
            const uint32_t ba = bK + (uint32_t)p*16*272 + koff;
            ldm_x4(ba, bw[p][0], bw[p][1], bw[p][2], bw[p][3]);
        }
        #pragma unroll
        for (int nt = 0; nt < 4; nt++) {
            const uint32_t* bp = &bw[nt >> 1][(nt & 1)*2];
            float* d = oacc[nt];
            mma16816h(d[0], d[1], d[2], d[3], ah[0], ah[1], ah[2], ah[3], bp[0], bp[1]);
        }
    }
    {   // intra
        const uint32_t aS = sb + CO_SC + (uint32_t)(wm*16 + (lane & 15))*144
                          + (uint32_t)(lane >> 4)*16;
        const uint32_t bV = sb + CO_VT + (uint32_t)(wn*32 + ((lane >> 4) & 1)*8 + (lane & 7))*144
                          + (uint32_t)((lane >> 3) & 1)*16;
        #pragma unroll
        for (int ks = 0; ks < 4; ks++) {
            const uint32_t koff = (uint32_t)ks*32;
            uint32_t ah[4];
            ldm_x4(aS + koff, ah[0], ah[1], ah[2], ah[3]);
            uint32_t bw[2][4];
            #pragma unroll
            for (int p = 0; p < 2; p++) {
                const uint32_t ba = bV + (uint32_t)p*16*144 + koff;
                ldm_x4(ba, bw[p][0], bw[p][1], bw[p][2], bw[p][3]);
            }
            #pragma unroll
            for (int nt = 0; nt < 4; nt++) {
                const uint32_t* bp = &bw[nt >> 1][(nt & 1)*2];
                float* d = oacc[nt];
                mma16816h(d[0], d[1], d[2], d[3], ah[0], ah[1], ah[2], ah[3], bp[0], bp[1]);
            }
        }
    }

    // write o single fp16 in [B,T,H*HD] layout
    #pragma unroll
    for (int nt = 0; nt < 4; nt++) {
        const int dcol = wn*32 + nt*8 + tq*2;
        const int r0 = wm*16 + g;
        #pragma unroll
        for (int half = 0; half < 2; half++) {
            const int r = r0 + half*8;
            const size_t oidx = ((size_t)(b*T_) + n*C_ + r)*D_ + h*HD_ + dcol;
            *(__half2*)(oh + oidx) =
                __halves2half2(__float2half_rn(oacc[nt][half*2]),
                               __float2half_rn(oacc[nt][half*2+1]));
        }
    }
}

// ---------------- launcher ----------------------------------------------------
extern "C" void kernel_launch(void* const* d_in, const int* in_sizes, int n_in,
                              void* d_out, int out_size)
{
    const float* hs   = (const float*)d_in[0];
    const float* res  = (const float*)d_in[1];
    const float* nw   = (const float*)d_in[2];
    const float* w_q  = (const float*)d_in[3];
    const float* w_k  = (const float*)d_in[4];
    const float* w_v  = (const float*)d_in[5];
    const float* w_o  = (const float*)d_in[6];
    const float* hqw  = (const float*)d_in[7];
    const float* hqb  = (const float*)d_in[8];
    const float* hkw  = (const float*)d_in[9];
    const float* hkb  = (const float*)d_in[10];
    float* out = (float*)d_out;

    __half *pkv, *pxh, *poh, *pwT, *pwo, *pqfh, *pkfh, *pvh, *pST;
    cudaGetSymbolAddress((void**)&pkv,  g_kv);
    cudaGetSymbolAddress((void**)&pxh,  g_xh);
    cudaGetSymbolAddress((void**)&poh,  g_oh);
    cudaGetSymbolAddress((void**)&pwT,  g_wT);
    cudaGetSymbolAddress((void**)&pwo,  g_woT);
    cudaGetSymbolAddress((void**)&pqfh, g_qfh);
    cudaGetSymbolAddress((void**)&pkfh, g_kfh);
    cudaGetSymbolAddress((void**)&pvh,  g_vh);
    cudaGetSymbolAddress((void**)&pST,  g_ST);

    const int fsmem = (128*65 + 64*64) * sizeof(float);   // 49664
    cudaFuncSetAttribute(weightprep_kernel,
                         cudaFuncAttributeMaxDynamicSharedMemorySize, fsmem);
    cudaFuncSetAttribute(gemm_qkv,
                         cudaFuncAttributeMaxDynamicSharedMemorySize, GSMEM);
    cudaFuncSetAttribute(gemm_o,
                         cudaFuncAttributeMaxDynamicSharedMemorySize, GSMEM);
    cudaFuncSetAttribute(chunk_kv_kernel,
                         cudaFuncAttributeMaxDynamicSharedMemorySize, CKV_SMEM);
    cudaFuncSetAttribute(chunk_out_kernel,
                         cudaFuncAttributeMaxDynamicSharedMemorySize, CO_SMEM);

    // 1) weight prep (fold hedgehog into q/k; transpose v, o) -> fp16
    weightprep_kernel<<<dim3(16, 8, 4), 256, fsmem>>>(w_q, w_k, w_v, w_o, hqw, hkw, pwT, pwo);

    // 2) fused add + RMSNorm
    addnorm_kernel<<<BT_, 256>>>(hs, res, nw, out + (size_t)BT_*D_, pxh);

    // 3) fused QKV projection + hedgehog epilogue
    dim3 qkvgrid(24, BT_/128);
    gemm_qkv<<<qkvgrid, 256, GSMEM>>>(pxh, pwT, hqb, hkb, pqfh, pkfh, pvh);

    // 4) chunked linear attention (profiler slot #4 -> chunk_kv)
    chunk_kv_kernel<<<NCHUNK_, 256, CKV_SMEM>>>(pkfh, pvh, pkv);
    kv_scan_kernel<<<512, 1024>>>(pkv, pST);
    chunk_out_kernel<<<NCHUNK_, 256, CO_SMEM>>>(pqfh, pkfh, pvh, pST, poh);

    // 5) output projection
    gemm_o<<<dim3(8, BT_/128), 256, GSMEM>>>(poh, pwo, out);
}

// round 15
// speedup vs baseline: 1.0967x; 1.0291x over previous
#include <cuda_runtime.h>
#include <cuda_bf16.h>
#include <cuda_fp16.h>
#include <stdint.h>
#include <math.h>

// Problem constants
#define B_  4
#define T_  2048
#define D_  1024
#define H_  16
#define HD_ 64
#define F_  128
#define C_  64
#define N_  32
#define BT_ (B_*T_)        // 8192
#define BHT_ (B_*H_*T_)    // 131072
#define NCHUNK_ (B_*H_*N_) // 2048

// ---------------- scratch (device globals) ----------------------------------
__device__ __half g_kv [NCHUNK_*F_*HD_];        // kv^T per chunk (fp16)
__device__ __half g_ST [NCHUNK_*F_*HD_];        // S_excl^T single fp16
__device__ __half g_qfh[BHT_*F_];               // q features single fp16
__device__ __half g_kfh[BHT_*F_];               // k features single fp16
__device__ __half g_vh [BT_*D_];                // v single fp16
__device__ __half g_xh [BT_*D_];                // x single fp16
__device__ __half g_oh [BT_*D_];                // attention out single fp16
__device__ __half g_wT [3*D_*D_];               // fused qkv weights, fp16 single
__device__ __half g_woT[D_*D_];                 // o weights, fp16 single

// ---------------- PTX helpers ------------------------------------------------
__device__ __forceinline__ uint32_t smem_u32(const void* p) {
    uint32_t a;
    asm("{ .reg .u64 t; cvta.to.shared.u64 t, %1; cvt.u32.u64 %0, t; }" : "=r"(a) : "l"(p));
    return a;
}
__device__ __forceinline__ void cp_async16(uint32_t saddr, const void* gaddr) {
    asm volatile("cp.async.cg.shared.global [%0], [%1], 16;" :: "r"(saddr), "l"(gaddr));
}
__device__ __forceinline__ void cp_commit() {
    asm volatile("cp.async.commit_group;" ::: "memory");
}
template <int NN>
__device__ __forceinline__ void cp_wait() {
    asm volatile("cp.async.wait_group %0;" :: "n"(NN) : "memory");
}
__device__ __forceinline__ void ldm_x4(uint32_t addr, uint32_t& r0, uint32_t& r1,
                                       uint32_t& r2, uint32_t& r3) {
    asm volatile("ldmatrix.sync.aligned.m8n8.x4.shared.b16 {%0,%1,%2,%3}, [%4];"
                 : "=r"(r0), "=r"(r1), "=r"(r2), "=r"(r3) : "r"(addr));
}
__device__ __forceinline__ void ldm_x4t(uint32_t addr, uint32_t& r0, uint32_t& r1,
                                        uint32_t& r2, uint32_t& r3) {
    asm volatile("ldmatrix.sync.aligned.m8n8.x4.trans.shared.b16 {%0,%1,%2,%3}, [%4];"
                 : "=r"(r0), "=r"(r1), "=r"(r2), "=r"(r3) : "r"(addr));
}
__device__ __forceinline__ void mma16816h(float& d0, float& d1, float& d2, float& d3,
                                          uint32_t a0, uint32_t a1, uint32_t a2, uint32_t a3,
                                          uint32_t b0, uint32_t b1) {
    asm volatile("mma.sync.aligned.m16n8k16.row.col.f32.f16.f16.f32 "
                 "{%0,%1,%2,%3}, {%4,%5,%6,%7}, {%8,%9}, {%0,%1,%2,%3};"
                 : "+f"(d0), "+f"(d1), "+f"(d2), "+f"(d3)
                 : "r"(a0), "r"(a1), "r"(a2), "r"(a3), "r"(b0), "r"(b1));
}

// ---------------- weight prep: fold/transpose -> fp16, z-dispatched ----------
__global__ __launch_bounds__(256)
void weightprep_kernel(const float* __restrict__ wq, const float* __restrict__ wk,
                       const float* __restrict__ wv, const float* __restrict__ wo,
                       const float* __restrict__ hqw, const float* __restrict__ hkw,
                       __half* __restrict__ wT, __half* __restrict__ woT)
{
    extern __shared__ float fsm[];
    float* Wb = fsm;               // [128][65]
    float* hh = fsm + 128*65;      // [64][64]
    const int z = blockIdx.z;
    const float* W   = (z==0) ? wq : (z==1) ? wk : (z==2) ? wv : wo;
    const float* hhw = (z==0) ? hqw : (z==1) ? hkw : nullptr;
    __half* dst = (z==3) ? woT : wT;
    const int rowOff = (z==0) ? 0 : (z==1) ? 1024 : (z==2) ? 2048 : 0;

    const int h = blockIdx.x, kb = blockIdx.y;
    const int tid = threadIdx.x;
    for (int i = tid; i < 8192; i += 256) {
        int r = i >> 6, d = i & 63;
        Wb[r*65 + d] = W[(size_t)(kb*128 + r)*D_ + h*64 + d];
    }
    if (hhw)
        for (int i = tid; i < 4096; i += 256) hh[i] = hhw[i];
    __syncthreads();

    const int kk = tid & 127;
    const int e0 = (tid >> 7) * 32;
    float acc[32];
    if (hhw) {
        #pragma unroll
        for (int e = 0; e < 32; e++) acc[e] = 0.f;
        for (int d = 0; d < 64; d++) {
            float wv2 = Wb[kk*65 + d];
            #pragma unroll
            for (int e = 0; e < 32; e++)
                acc[e] = fmaf(wv2, hh[(e0+e)*64 + d], acc[e]);
        }
    } else {
        #pragma unroll
        for (int e = 0; e < 32; e++) acc[e] = Wb[kk*65 + e0 + e];
    }
    #pragma unroll
    for (int e = 0; e < 32; e++) {
        size_t idx = (size_t)(rowOff + h*64 + e0 + e)*D_ + kb*128 + kk;
        dst[idx] = __float2half_rn(acc[e]);
    }
}

// ---------------- fused add + RMSNorm -> resid + fp16 x ----------------------
__global__ __launch_bounds__(256)
void addnorm_kernel(const float* __restrict__ hs, const float* __restrict__ res,
                    const float* __restrict__ w, float* __restrict__ resid_out,
                    __half* __restrict__ xh)
{
    __shared__ float red[8];
    const int row = blockIdx.x;
    const int t = threadIdx.x;
    const float4* h4 = (const float4*)(hs  + (size_t)row*D_);
    const float4* r4 = (const float4*)(res + (size_t)row*D_);
    float4*      ro4 = (float4*)(resid_out + (size_t)row*D_);

    float4 h = h4[t], r = r4[t];
    float4 s = make_float4(h.x+r.x, h.y+r.y, h.z+r.z, h.w+r.w);
    ro4[t] = s;
    float ss = s.x*s.x + s.y*s.y + s.z*s.z + s.w*s.w;
    #pragma unroll
    for (int o = 16; o; o >>= 1) ss += __shfl_xor_sync(0xffffffffu, ss, o);
    if ((t & 31) == 0) red[t >> 5] = ss;
    __syncthreads();
    float tot = 0.f;
    #pragma unroll
    for (int i = 0; i < 8; i++) tot += red[i];
    float rstd = rsqrtf(tot * (1.0f/1024.0f) + 1e-5f);
    float4 wv = ((const float4*)w)[t];
    size_t idx = (size_t)row*D_ + t*4;
    *(__half2*)(xh+idx)   = __halves2half2(__float2half_rn(s.x*rstd*wv.x),
                                           __float2half_rn(s.y*rstd*wv.y));
    *(__half2*)(xh+idx+2) = __halves2half2(__float2half_rn(s.z*rstd*wv.z),
                                           __float2half_rn(s.w*rstd*wv.w));
}

// ---------------- fp16 fused QKV GEMM + hedgehog epilogue ---------------------
#define PITCH 40
#define MAT_BYTES (128*PITCH*2)          // 10240
#define STAGEB (2*MAT_BYTES)             // 20480
#define GSMEM (4*STAGEB)                 // 81920

__global__ __launch_bounds__(256, 2)
void gemm_qkv(const __half* __restrict__ Ah, const __half* __restrict__ W,
              const float* __restrict__ biasq, const float* __restrict__ biask,
              __half* __restrict__ Qfh, __half* __restrict__ Kfh,
              __half* __restrict__ Vh)
{
    extern __shared__ __align__(16) char smem[];
    const uint32_t sbase = smem_u32(smem);
    const int tid = threadIdx.x, wid = tid >> 5, lane = tid & 31;
    const int bx = blockIdx.x, by = blockIdx.y;
    const int wm = wid & 1, wn = wid >> 1;

    const int lrow = tid >> 1;
    const int lc   = (tid & 1) * 2;
    const size_t gA = (size_t)(by*128 + lrow) * D_;
    const size_t gB = (size_t)(bx*128 + lrow) * D_;
    const uint32_t sRow = (uint32_t)lrow * 80;

    float acc[4][4][4];
    #pragma unroll
    for (int i = 0; i < 4; i++)
        #pragma unroll
        for (int j = 0; j < 4; j++)
            #pragma unroll
            for (int l = 0; l < 4; l++) acc[i][j][l] = 0.f;

    #define PREFETCH(kt, buf) do {                                              \
        const int k0 = (kt) * 32;                                               \
        const uint32_t b0 = sbase + (uint32_t)(buf) * STAGEB;                   \
        _Pragma("unroll")                                                       \
        for (int u = 0; u < 2; u++) {                                           \
            const int c = lc + u;                                               \
            const uint32_t so = sRow + (uint32_t)c * 16;                        \
            const size_t go = (size_t)k0 + c * 8;                               \
            cp_async16(b0 + 0*MAT_BYTES + so, Ah + gA + go);                    \
            cp_async16(b0 + 1*MAT_BYTES + so, W  + gB + go);                    \
        }                                                                       \
        cp_commit();                                                            \
    } while (0)

    PREFETCH(0, 0);
    PREFETCH(1, 1);
    PREFETCH(2, 2);

    const uint32_t aRow = (uint32_t)(wm*64 + (lane & 15)) * 80 + (uint32_t)(lane >> 4) * 16;
    const uint32_t bRow = (uint32_t)(wn*32 + ((lane >> 4) & 1)*8 + (lane & 7)) * 80
                        + (uint32_t)((lane >> 3) & 1) * 16;

    const int TILES = D_ / 32;   // 32
    int buf = 0;
    #pragma unroll 1
    for (int kt = 0; kt < TILES; kt++) {
        if (kt >= TILES - 3) cp_wait<0>(); else cp_wait<2>();
        __syncthreads();
        if (kt + 3 < TILES) {
            int b3 = buf + 3; if (b3 >= 4) b3 -= 4;
            PREFETCH(kt + 3, b3);
        }
        const uint32_t sb = sbase + (uint32_t)buf * STAGEB;

        #pragma unroll
        for (int kk = 0; kk < 2; kk++) {
            const uint32_t koff = (uint32_t)kk * 32;
            uint32_t bw[2][4];
            #pragma unroll
            for (int nt2 = 0; nt2 < 2; nt2++) {
                const uint32_t ba = bRow + (uint32_t)nt2 * 16 * 80 + koff;
                ldm_x4(sb + 1*MAT_BYTES + ba, bw[nt2][0], bw[nt2][1], bw[nt2][2], bw[nt2][3]);
            }
            #pragma unroll
            for (int mt = 0; mt < 4; mt++) {
                const uint32_t aa = aRow + (uint32_t)mt * 16 * 80 + koff;
                uint32_t ah[4];
                ldm_x4(sb + aa, ah[0], ah[1], ah[2], ah[3]);
                #pragma unroll
                for (int nt = 0; nt < 4; nt++) {
                    const uint32_t* bp = &bw[nt >> 1][(nt & 1) * 2];
                    float* d = acc[mt][nt];
                    mma16816h(d[0], d[1], d[2], d[3], ah[0], ah[1], ah[2], ah[3], bp[0], bp[1]);
                }
            }
        }
        buf++; if (buf == 4) buf = 0;
    }
    #undef PREFETCH
    __syncthreads();    // smem reuse below

    const int g = lane >> 2, tq = lane & 3;

    if (bx < 16) {
        const int isQ = (bx < 8);
        const float* bias = isQ ? biasq : biask;
        const float scale = isQ ? 0.08838834764831845f : 1.0f;
        __half* fh = isQ ? Qfh : Kfh;
        float* smax = (float*)smem;
        float* ssum = smax + 512;
        #pragma unroll
        for (int mt = 0; mt < 4; mt++) {
            float pm0 = 0.f, pm1 = 0.f;
            #pragma unroll
            for (int nt = 0; nt < 4; nt++) {
                const int cb = (wn*32 + nt*8 + tq*2) & 63;
                const float b0 = bias[cb], b1 = bias[cb + 1];
                float* d = acc[mt][nt];
                d[0] += b0; d[1] += b1; d[2] += b0; d[3] += b1;
                pm0 = fmaxf(pm0, fmaxf(fabsf(d[0]), fabsf(d[1])));
                pm1 = fmaxf(pm1, fmaxf(fabsf(d[2]), fabsf(d[3])));
            }
            pm0 = fmaxf(pm0, __shfl_xor_sync(0xffffffffu, pm0, 1));
            pm0 = fmaxf(pm0, __shfl_xor_sync(0xffffffffu, pm0, 2));
            pm1 = fmaxf(pm1, __shfl_xor_sync(0xffffffffu, pm1, 1));
            pm1 = fmaxf(pm1, __shfl_xor_sync(0xffffffffu, pm1, 2));
            if (tq == 0) {
                smax[wn*128 + wm*64 + mt*16 + g]     = pm0;
                smax[wn*128 + wm*64 + mt*16 + g + 8] = pm1;
            }
        }
        __syncthreads();
        float mrow[4][2];
        #pragma unroll
        for (int mt = 0; mt < 4; mt++) {
            #pragma unroll
            for (int half = 0; half < 2; half++) {
                const int r = wm*64 + mt*16 + g + half*8;
                mrow[mt][half] = fmaxf(smax[wn*128 + r], smax[(wn^1)*128 + r]);
            }
        }
        #pragma unroll
        for (int mt = 0; mt < 4; mt++) {
            float s0 = 0.f, s1 = 0.f;
            #pragma unroll
            for (int nt = 0; nt < 4; nt++) {
                const float* d = acc[mt][nt];
                s0 += __expf(d[0]-mrow[mt][0]) + __expf(-d[0]-mrow[mt][0])
                    + __expf(d[1]-mrow[mt][0]) + __expf(-d[1]-mrow[mt][0]);
                s1 += __expf(d[2]-mrow[mt][1]) + __expf(-d[2]-mrow[mt][1])
                    + __expf(d[3]-mrow[mt][1]) + __expf(-d[3]-mrow[mt][1]);
            }
            s0 += __shfl_xor_sync(0xffffffffu, s0, 1);
            s0 += __shfl_xor_sync(0xffffffffu, s0, 2);
            s1 += __shfl_xor_sync(0xffffffffu, s1, 1);
            s1 += __shfl_xor_sync(0xffffffffu, s1, 2);
            if (tq == 0) {
                ssum[wn*128 + wm*64 + mt*16 + g]     = s0;
                ssum[wn*128 + wm*64 + mt*16 + g + 8] = s1;
            }
        }
        __syncthreads();
        const int hloc = (bx & 7)*2 + (wn >> 1);
        #pragma unroll
        for (int mt = 0; mt < 4; mt++) {
            #pragma unroll
            for (int half = 0; half < 2; half++) {
                const int r = wm*64 + mt*16 + g + half*8;
                const float z = ssum[wn*128 + r] + ssum[(wn^1)*128 + r];
                const float inv = scale / z;
                const float mm = mrow[mt][half];
                const int rowg = by*128 + r;
                const int bb = rowg >> 11, tt = rowg & 2047;
                const size_t base = ((size_t)(bb*H_ + hloc)*T_ + tt)*F_;
                #pragma unroll
                for (int nt = 0; nt < 4; nt++) {
                    const int f = (wn*32 + nt*8 + tq*2) & 63;
                    const float y0 = acc[mt][nt][half*2], y1 = acc[mt][nt][half*2+1];
                    const float p0 = __expf(y0 - mm)*inv,  p1 = __expf(y1 - mm)*inv;
                    const float n0 = __expf(-y0 - mm)*inv, n1 = __expf(-y1 - mm)*inv;
                    *(__half2*)(fh + base + f) =
                        __halves2half2(__float2half_rn(p0), __float2half_rn(p1));
                    *(__half2*)(fh + base + 64 + f) =
                        __halves2half2(__float2half_rn(n0), __float2half_rn(n1));
                }
            }
        }
    } else {
        const int colbase = (bx - 16)*128;
        #pragma unroll
        for (int mt = 0; mt < 4; mt++) {
            const int r0 = by*128 + wm*64 + mt*16 + g;
            #pragma unroll
            for (int nt = 0; nt < 4; nt++) {
                const int col = colbase + wn*32 + nt*8 + tq*2;
                float* d = acc[mt][nt];
                *(__half2*)(Vh + (size_t)r0*D_ + col) =
                    __halves2half2(__float2half_rn(d[0]), __float2half_rn(d[1]));
                *(__half2*)(Vh + (size_t)(r0+8)*D_ + col) =
                    __halves2half2(__float2half_rn(d[2]), __float2half_rn(d[3]));
            }
        }
    }
}

// ---------------- fp16 GEMM (fp32 out; o-projection) --------------------------
__global__ __launch_bounds__(256, 2)
void gemm_o(const __half* __restrict__ Ah, const __half* __restrict__ W,
            float* __restrict__ Cout)
{
    extern __shared__ __align__(16) char smem[];
    const uint32_t sbase = smem_u32(smem);
    const int tid = threadIdx.x, wid = tid >> 5, lane = tid & 31;
    const int bx = blockIdx.x, by = blockIdx.y;
    const int wm = wid & 1, wn = wid >> 1;

    const int lrow = tid >> 1;
    const int lc   = (tid & 1) * 2;
    const size_t gA = (size_t)(by*128 + lrow) * D_;
    const size_t gB = (size_t)(bx*128 + lrow) * D_;
    const uint32_t sRow = (uint32_t)lrow * 80;

    float acc[4][4][4];
    #pragma unroll
    for (int i = 0; i < 4; i++)
        #pragma unroll
        for (int j = 0; j < 4; j++)
            #pragma unroll
            for (int l = 0; l < 4; l++) acc[i][j][l] = 0.f;

    #define PREFETCH(kt, buf) do {                                              \
        const int k0 = (kt) * 32;                                               \
        const uint32_t b0 = sbase + (uint32_t)(buf) * STAGEB;                   \
        _Pragma("unroll")                                                       \
        for (int u = 0; u < 2; u++) {                                           \
            const int c = lc + u;                                               \
            const uint32_t so = sRow + (uint32_t)c * 16;                        \
            const size_t go = (size_t)k0 + c * 8;                               \
            cp_async16(b0 + 0*MAT_BYTES + so, Ah + gA + go);                    \
            cp_async16(b0 + 1*MAT_BYTES + so, W  + gB + go);                    \
        }                                                                       \
        cp_commit();                                                            \
    } while (0)

    PREFETCH(0, 0);
    PREFETCH(1, 1);
    PREFETCH(2, 2);

    const uint32_t aRow = (uint32_t)(wm*64 + (lane & 15)) * 80 + (uint32_t)(lane >> 4) * 16;
    const uint32_t bRow = (uint32_t)(wn*32 + ((lane >> 4) & 1)*8 + (lane & 7)) * 80
                        + (uint32_t)((lane >> 3) & 1) * 16;

    const int TILES = D_ / 32;
    int buf = 0;
    #pragma unroll 1
    for (int kt = 0; kt < TILES; kt++) {
        if (kt >= TILES - 3) cp_wait<0>(); else cp_wait<2>();
        __syncthreads();
        if (kt + 3 < TILES) {
            int b3 = buf + 3; if (b3 >= 4) b3 -= 4;
            PREFETCH(kt + 3, b3);
        }
        const uint32_t sb = sbase + (uint32_t)buf * STAGEB;

        #pragma unroll
        for (int kk = 0; kk < 2; kk++) {
            const uint32_t koff = (uint32_t)kk * 32;
            uint32_t bw[2][4];
            #pragma unroll
            for (int nt2 = 0; nt2 < 2; nt2++) {
                const uint32_t ba = bRow + (uint32_t)nt2 * 16 * 80 + koff;
                ldm_x4(sb + 1*MAT_BYTES + ba, bw[nt2][0], bw[nt2][1], bw[nt2][2], bw[nt2][3]);
            }
            #pragma unroll
            for (int mt = 0; mt < 4; mt++) {
                const uint32_t aa = aRow + (uint32_t)mt * 16 * 80 + koff;
                uint32_t ah[4];
                ldm_x4(sb + aa, ah[0], ah[1], ah[2], ah[3]);
                #pragma unroll
                for (int nt = 0; nt < 4; nt++) {
                    const uint32_t* bp = &bw[nt >> 1][(nt & 1) * 2];
                    float* d = acc[mt][nt];
                    mma16816h(d[0], d[1], d[2], d[3], ah[0], ah[1], ah[2], ah[3], bp[0], bp[1]);
                }
            }
        }
        buf++; if (buf == 4) buf = 0;
    }
    #undef PREFETCH

    const int g = lane >> 2, tq = lane & 3;
    #pragma unroll
    for (int mt = 0; mt < 4; mt++) {
        const int r0 = by*128 + wm*64 + mt*16 + g;
        #pragma unroll
        for (int nt = 0; nt < 4; nt++) {
            const int col = bx*128 + wn*32 + nt*8 + tq*2;
            float* d = acc[mt][nt];
            *(float2*)(Cout + (size_t)r0*D_ + col)     = make_float2(d[0], d[1]);
            *(float2*)(Cout + (size_t)(r0+8)*D_ + col) = make_float2(d[2], d[3]);
        }
    }
}

// ---------------- phase A: kv^T[d][f] = sum_c v[c,d] k[c,f] -------------------
// Natural layouts + ldmatrix.trans (no scalar transposes).
// k [64 c][128 f] pitch 272 at 0 (17408); v [64 c][64 d] pitch 144 at 17408 (9216).
#define CKV_K   0u
#define CKV_V   17408u
#define CKV_SMEM 26624u

__global__ __launch_bounds__(256, 3)
void chunk_kv_kernel(const __half* __restrict__ kfh,
                     const __half* __restrict__ vh,
                     __half* __restrict__ kvT)
{
    extern __shared__ __align__(16) char smem[];
    const uint32_t sb = smem_u32(smem);
    const int blk = blockIdx.x;
    const int n = blk & 31, bh = blk >> 5;
    const int b = bh >> 4, h = bh & 15;
    const int tid = threadIdx.x, wid = tid >> 5, lane = tid & 31;

    // natural staging (vectorized)
    {
        const int c = tid >> 2, fg = (tid & 3) * 32;
        const size_t src = ((size_t)bh*T_ + n*C_ + c)*F_ + fg;
        uint4* dk = (uint4*)(smem + CKV_K + c*272 + fg*2);
        #pragma unroll
        for (int q = 0; q < 4; q++) dk[q] = *(const uint4*)(kfh + src + q*8);
    }
    {
        const int c = tid >> 2, dg = (tid & 3) * 16;
        const size_t src = ((size_t)(b*T_) + n*C_ + c)*D_ + h*HD_ + dg;
        uint4* dv = (uint4*)(smem + CKV_V + c*144 + dg*2);
        #pragma unroll
        for (int q = 0; q < 2; q++) dv[q] = *(const uint4*)(vh + src + q*8);
    }
    __syncthreads();

    const int wm = wid & 3, wn = wid >> 2;
    float acc[8][4];
    #pragma unroll
    for (int i = 0; i < 8; i++)
        #pragma unroll
        for (int j = 0; j < 4; j++) acc[i][j] = 0.f;

    // A (v, trans): row = c + ((lane>>4)&1)*8 + (lane&7), col = wm*16 + ((lane>>3)&1)*8
    const uint32_t aBase = sb + CKV_V
        + (uint32_t)(((lane >> 4) & 1)*8 + (lane & 7)) * 144
        + (uint32_t)(wm*16 + ((lane >> 3) & 1)*8) * 2;
    // B (k, trans): row = c + ((lane>>3)&1)*8 + (lane&7), col = wn*64 + p*16 + ((lane>>4)&1)*8
    const uint32_t bBase = sb + CKV_K
        + (uint32_t)(((lane >> 3) & 1)*8 + (lane & 7)) * 272
        + (uint32_t)(wn*64 + ((lane >> 4) & 1)*8) * 2;

    #pragma unroll
    for (int ks = 0; ks < 4; ks++) {
        uint32_t ah[4];
        ldm_x4t(aBase + (uint32_t)ks*16*144, ah[0], ah[1], ah[2], ah[3]);
        uint32_t bw[4][4];
        #pragma unroll
        for (int p = 0; p < 4; p++) {
            ldm_x4t(bBase + (uint32_t)ks*16*272 + (uint32_t)p*32,
                    bw[p][0], bw[p][1], bw[p][2], bw[p][3]);
        }
        #pragma unroll
        for (int nt = 0; nt < 8; nt++) {
            const uint32_t* bp = &bw[nt >> 1][(nt & 1)*2];
            float* d = acc[nt];
            mma16816h(d[0], d[1], d[2], d[3], ah[0], ah[1], ah[2], ah[3], bp[0], bp[1]);
        }
    }
    const int g = lane >> 2, tq = lane & 3;
    __half* out = kvT + (size_t)blk * (F_*HD_);
    #pragma unroll
    for (int nt = 0; nt < 8; nt++) {
        const int f = wn*64 + nt*8 + tq*2;
        const int d0 = wm*16 + g;
        *(__half2*)(out + (size_t)d0*F_ + f) =
            __halves2half2(__float2half_rn(acc[nt][0]), __float2half_rn(acc[nt][1]));
        *(__half2*)(out + (size_t)(d0+8)*F_ + f) =
            __halves2half2(__float2half_rn(acc[nt][2]), __float2half_rn(acc[nt][3]));
    }
}

// ---------------- phase B: exclusive cumsum (fp32 acc) -> single fp16 --------
__global__ __launch_bounds__(1024)
void kv_scan_kernel(const __half* __restrict__ kvT, __half* __restrict__ ST)
{
    const int blk = blockIdx.x;
    const int bh = blk >> 3, seg = blk & 7;
    const int e = seg*1024 + threadIdx.x;
    size_t base = (size_t)bh * N_ * (F_*HD_) + e;
    float acc = 0.f;
    for (int n = 0; n < N_; n++) {
        size_t idx = base + (size_t)n * (F_*HD_);
        ST[idx] = __float2half_rn(acc);
        acc += __half2float(kvT[idx]);
    }
}

// ---------------- phase C: out = q@S_excl + tril(q@k^T)@v ---------------------
// q,k natural [c][f] p272; ST [d][f] p272 (overwrites k); v natural [c][d] p144;
// scores [c][m] p144. v B-fragments loaded via ldmatrix.trans.
#define CO_Q   0u          // 17408
#define CO_K   17408u      // 17408
#define CO_V   34816u      // 9216
#define CO_SC  44032u      // 9216
#define CO_SMEM 53248u

__global__ __launch_bounds__(256, 3)
void chunk_out_kernel(const __half* __restrict__ qfh,
                      const __half* __restrict__ kfh,
                      const __half* __restrict__ vh,
                      const __half* __restrict__ ST,
                      __half* __restrict__ oh)
{
    extern __shared__ __align__(16) char smem[];
    const uint32_t sb = smem_u32(smem);
    const int blk = blockIdx.x;
    const int n = blk & 31, bh = blk >> 5;
    const int b = bh >> 4, h = bh & 15;
    const int tid = threadIdx.x, wid = tid >> 5, lane = tid & 31;

    {
        const int c = tid >> 2, fg = (tid & 3) * 32;
        const size_t src = ((size_t)bh*T_ + n*C_ + c)*F_ + fg;
        uint4* dq = (uint4*)(smem + CO_Q + c*272 + fg*2);
        uint4* dk = (uint4*)(smem + CO_K + c*272 + fg*2);
        #pragma unroll
        for (int q = 0; q < 4; q++) {
            dq[q] = *(const uint4*)(qfh + src + q*8);
            dk[q] = *(const uint4*)(kfh + src + q*8);
        }
    }
    {
        const int c = tid >> 2, dg = (tid & 3) * 16;
        const size_t src = ((size_t)(b*T_) + n*C_ + c)*D_ + h*HD_ + dg;
        uint4* dv = (uint4*)(smem + CO_V + c*144 + dg*2);
        #pragma unroll
        for (int q = 0; q < 2; q++) dv[q] = *(const uint4*)(vh + src + q*8);
    }
    __syncthreads();

    const int wm = wid & 3, wn = wid >> 2;
    const int g = lane >> 2, tq = lane & 3;

    const uint32_t aQ = sb + CO_Q + (uint32_t)(wm*16 + (lane & 15))*272 + (uint32_t)(lane >> 4)*16;
    const uint32_t bK = sb + CO_K + (uint32_t)(wn*32 + ((lane >> 4) & 1)*8 + (lane & 7))*272
                      + (uint32_t)((lane >> 3) & 1)*16;

    // ---- scores = q @ k^T ----
    float sacc[4][4];
    #pragma unroll
    for (int i = 0; i < 4; i++)
        #pragma unroll
        for (int j = 0; j < 4; j++) sacc[i][j] = 0.f;

    #pragma unroll
    for (int ks = 0; ks < 8; ks++) {
        const uint32_t koff = (uint32_t)ks*32;
        uint32_t ah[4];
        ldm_x4(aQ + koff, ah[0], ah[1], ah[2], ah[3]);
        uint32_t bw[2][4];
        #pragma unroll
        for (int p = 0; p < 2; p++) {
            const uint32_t ba = bK + (uint32_t)p*16*272 + koff;
            ldm_x4(ba, bw[p][0], bw[p][1], bw[p][2], bw[p][3]);
        }
        #pragma unroll
        for (int nt = 0; nt < 4; nt++) {
            const uint32_t* bp = &bw[nt >> 1][(nt & 1)*2];
            float* d = sacc[nt];
            mma16816h(d[0], d[1], d[2], d[3], ah[0], ah[1], ah[2], ah[3], bp[0], bp[1]);
        }
    }
    #pragma unroll
    for (int nt = 0; nt < 4; nt++) {
        const int colb = wn*32 + nt*8 + tq*2;
        const int r0 = wm*16 + g, r1 = r0 + 8;
        float v00 = (colb     <= r0) ? sacc[nt][0] : 0.f;
        float v01 = (colb + 1 <= r0) ? sacc[nt][1] : 0.f;
        float v10 = (colb     <= r1) ? sacc[nt][2] : 0.f;
        float v11 = (colb + 1 <= r1) ? sacc[nt][3] : 0.f;
        *(__half2*)(smem + CO_SC + r0*144 + colb*2) =
            __halves2half2(__float2half_rn(v00), __float2half_rn(v01));
        *(__half2*)(smem + CO_SC + r1*144 + colb*2) =
            __halves2half2(__float2half_rn(v10), __float2half_rn(v11));
    }
    __syncthreads();

    {
        const int d = tid >> 2, fg = (tid & 3) * 32;
        const size_t src = (size_t)blk*(F_*HD_) + d*F_ + fg;
        uint4* dh = (uint4*)(smem + CO_K + d*272 + fg*2);
        #pragma unroll
        for (int q = 0; q < 4; q++)
            dh[q] = *(const uint4*)(ST + src + q*8);
    }
    __syncthreads();

    // ---- out = q @ S_excl + scores @ v ----
    float oacc[4][4];
    #pragma unroll
    for (int i = 0; i < 4; i++)
        #pragma unroll
        for (int j = 0; j < 4; j++) oacc[i][j] = 0.f;

    #pragma unroll
    for (int ks = 0; ks < 8; ks++) {     // inter
        const uint32_t koff = (uint32_t)ks*32;
        uint32_t ah[4];
        ldm_x4(aQ + koff, ah[0], ah[1], ah[2], ah[3]);
        uint32_t bw[2][4];
        #pragma unroll
        for (int p = 0; p < 2; p++) {
            const uint32_t ba = bK + (uint32_t)p*16*272 + koff;
            ldm_x4(ba, bw[p][0], bw[p][1], bw[p][2], bw[p][3]);
        }
        #pragma unroll
        for (int nt = 0; nt < 4; nt++) {
            const uint32_t* bp = &bw[nt >> 1][(nt & 1)*2];
            float* d = oacc[nt];
            mma16816h(d[0], d[1], d[2], d[3], ah[0], ah[1], ah[2], ah[3], bp[0], bp[1]);
        }
    }
    {   // intra: A = scores (normal), B = v via trans
        const uint32_t aS = sb + CO_SC + (uint32_t)(wm*16 + (lane & 15))*144
                          + (uint32_t)(lane >> 4)*16;
        // B (v, trans): row = c + ((lane>>3)&1)*8 + (lane&7),
        //               col = wn*32 + p*16 + ((lane>>4)&1)*8
        const uint32_t bV = sb + CO_V
            + (uint32_t)(((lane >> 3) & 1)*8 + (lane & 7)) * 144
            + (uint32_t)(wn*32 + ((lane >> 4) & 1)*8) * 2;
        #pragma unroll
        for (int ks = 0; ks < 4; ks++) {
            uint32_t ah[4];
            ldm_x4(aS + (uint32_t)ks*32, ah[0], ah[1], ah[2], ah[3]);
            uint32_t bw[2][4];
            #pragma unroll
            for (int p = 0; p < 2; p++) {
                ldm_x4t(bV + (uint32_t)ks*16*144 + (uint32_t)p*32,
                        bw[p][0], bw[p][1], bw[p][2], bw[p][3]);
            }
            #pragma unroll
            for (int nt = 0; nt < 4; nt++) {
                const uint32_t* bp = &bw[nt >> 1][(nt & 1)*2];
                float* d = oacc[nt];
                mma16816h(d[0], d[1], d[2], d[3], ah[0], ah[1], ah[2], ah[3], bp[0], bp[1]);
            }
        }
    }

    // write o single fp16 in [B,T,H*HD] layout
    #pragma unroll
    for (int nt = 0; nt < 4; nt++) {
        const int dcol = wn*32 + nt*8 + tq*2;
        const int r0 = wm*16 + g;
        #pragma unroll
        for (int half = 0; half < 2; half++) {
            const int r = r0 + half*8;
            const size_t oidx = ((size_t)(b*T_) + n*C_ + r)*D_ + h*HD_ + dcol;
            *(__half2*)(oh + oidx) =
                __halves2half2(__float2half_rn(oacc[nt][half*2]),
                               __float2half_rn(oacc[nt][half*2+1]));
        }
    }
}

// ---------------- launcher ----------------------------------------------------
extern "C" void kernel_launch(void* const* d_in, const int* in_sizes, int n_in,
                              void* d_out, int out_size)
{
    const float* hs   = (const float*)d_in[0];
    const float* res  = (const float*)d_in[1];
    const float* nw   = (const float*)d_in[2];
    const float* w_q  = (const float*)d_in[3];
    const float* w_k  = (const float*)d_in[4];
    const float* w_v  = (const float*)d_in[5];
    const float* w_o  = (const float*)d_in[6];
    const float* hqw  = (const float*)d_in[7];
    const float* hqb  = (const float*)d_in[8];
    const float* hkw  = (const float*)d_in[9];
    const float* hkb  = (const float*)d_in[10];
    float* out = (float*)d_out;

    __half *pkv, *pxh, *poh, *pwT, *pwo, *pqfh, *pkfh, *pvh, *pST;
    cudaGetSymbolAddress((void**)&pkv,  g_kv);
    cudaGetSymbolAddress((void**)&pxh,  g_xh);
    cudaGetSymbolAddress((void**)&poh,  g_oh);
    cudaGetSymbolAddress((void**)&pwT,  g_wT);
    cudaGetSymbolAddress((void**)&pwo,  g_woT);
    cudaGetSymbolAddress((void**)&pqfh, g_qfh);
    cudaGetSymbolAddress((void**)&pkfh, g_kfh);
    cudaGetSymbolAddress((void**)&pvh,  g_vh);
    cudaGetSymbolAddress((void**)&pST,  g_ST);

    const int fsmem = (128*65 + 64*64) * sizeof(float);   // 49664
    cudaFuncSetAttribute(weightprep_kernel,
                         cudaFuncAttributeMaxDynamicSharedMemorySize, fsmem);
    cudaFuncSetAttribute(gemm_qkv,
                         cudaFuncAttributeMaxDynamicSharedMemorySize, GSMEM);
    cudaFuncSetAttribute(gemm_o,
                         cudaFuncAttributeMaxDynamicSharedMemorySize, GSMEM);
    cudaFuncSetAttribute(chunk_kv_kernel,
                         cudaFuncAttributeMaxDynamicSharedMemorySize, CKV_SMEM);
    cudaFuncSetAttribute(chunk_out_kernel,
                         cudaFuncAttributeMaxDynamicSharedMemorySize, CO_SMEM);

    // 1) weight prep (fold hedgehog into q/k; transpose v, o) -> fp16
    weightprep_kernel<<<dim3(16, 8, 4), 256, fsmem>>>(w_q, w_k, w_v, w_o, hqw, hkw, pwT, pwo);

    // 2) fused add + RMSNorm
    addnorm_kernel<<<BT_, 256>>>(hs, res, nw, out + (size_t)BT_*D_, pxh);

    // 3) fused QKV projection + hedgehog epilogue
    dim3 qkvgrid(24, BT_/128);
    gemm_qkv<<<qkvgrid, 256, GSMEM>>>(pxh, pwT, hqb, hkb, pqfh, pkfh, pvh);

    // 4) chunked linear attention (ldmatrix.trans, no smem transposes)
    chunk_kv_kernel<<<NCHUNK_, 256, CKV_SMEM>>>(pkfh, pvh, pkv);
    kv_scan_kernel<<<512, 1024>>>(pkv, pST);
    chunk_out_kernel<<<NCHUNK_, 256, CO_SMEM>>>(pqfh, pkfh, pvh, pST, poh);

    // 5) output projection
    gemm_o<<<dim3(8, BT_/128), 256, GSMEM>>>(poh, pwo, out);
}

// round 16
// speedup vs baseline: 1.1228x; 1.0238x over previous
#include <cuda_runtime.h>
#include <cuda_bf16.h>
#include <cuda_fp16.h>
#include <stdint.h>
#include <math.h>

// Problem constants
#define B_  4
#define T_  2048
#define D_  1024
#define H_  16
#define HD_ 64
#define F_  128
#define C_  64
#define N_  32
#define BT_ (B_*T_)        // 8192
#define BHT_ (B_*H_*T_)    // 131072
#define NCHUNK_ (B_*H_*N_) // 2048

// ---------------- scratch (device globals) ----------------------------------
__device__ __half g_kv [NCHUNK_*F_*HD_];        // kv^T per chunk (fp16)
__device__ __half g_ST [NCHUNK_*F_*HD_];        // S_excl^T single fp16
__device__ __half g_qfh[BHT_*F_];               // q features single fp16
__device__ __half g_kfh[BHT_*F_];               // k features single fp16
__device__ __half g_vh [BT_*D_];                // v single fp16
__device__ __half g_xh [BT_*D_];                // x single fp16
__device__ __half g_oh [BT_*D_];                // attention out single fp16
__device__ __half g_wT [3*D_*D_];               // fused qkv weights, fp16 single
__device__ __half g_woT[D_*D_];                 // o weights, fp16 single

// ---------------- PTX helpers ------------------------------------------------
__device__ __forceinline__ uint32_t smem_u32(const void* p) {
    uint32_t a;
    asm("{ .reg .u64 t; cvta.to.shared.u64 t, %1; cvt.u32.u64 %0, t; }" : "=r"(a) : "l"(p));
    return a;
}
__device__ __forceinline__ void cp_async16(uint32_t saddr, const void* gaddr) {
    asm volatile("cp.async.cg.shared.global [%0], [%1], 16;" :: "r"(saddr), "l"(gaddr));
}
__device__ __forceinline__ void cp_commit() {
    asm volatile("cp.async.commit_group;" ::: "memory");
}
template <int NN>
__device__ __forceinline__ void cp_wait() {
    asm volatile("cp.async.wait_group %0;" :: "n"(NN) : "memory");
}
__device__ __forceinline__ void ldm_x4(uint32_t addr, uint32_t& r0, uint32_t& r1,
                                       uint32_t& r2, uint32_t& r3) {
    asm volatile("ldmatrix.sync.aligned.m8n8.x4.shared.b16 {%0,%1,%2,%3}, [%4];"
                 : "=r"(r0), "=r"(r1), "=r"(r2), "=r"(r3) : "r"(addr));
}
__device__ __forceinline__ void ldm_x4t(uint32_t addr, uint32_t& r0, uint32_t& r1,
                                        uint32_t& r2, uint32_t& r3) {
    asm volatile("ldmatrix.sync.aligned.m8n8.x4.trans.shared.b16 {%0,%1,%2,%3}, [%4];"
                 : "=r"(r0), "=r"(r1), "=r"(r2), "=r"(r3) : "r"(addr));
}
__device__ __forceinline__ void mma16816h(float& d0, float& d1, float& d2, float& d3,
                                          uint32_t a0, uint32_t a1, uint32_t a2, uint32_t a3,
                                          uint32_t b0, uint32_t b1) {
    asm volatile("mma.sync.aligned.m16n8k16.row.col.f32.f16.f16.f32 "
                 "{%0,%1,%2,%3}, {%4,%5,%6,%7}, {%8,%9}, {%0,%1,%2,%3};"
                 : "+f"(d0), "+f"(d1), "+f"(d2), "+f"(d3)
                 : "r"(a0), "r"(a1), "r"(a2), "r"(a3), "r"(b0), "r"(b1));
}

// ---------------- weight prep: fold/transpose -> fp16, z-dispatched ----------
__global__ __launch_bounds__(256)
void weightprep_kernel(const float* __restrict__ wq, const float* __restrict__ wk,
                       const float* __restrict__ wv, const float* __restrict__ wo,
                       const float* __restrict__ hqw, const float* __restrict__ hkw,
                       __half* __restrict__ wT, __half* __restrict__ woT)
{
    extern __shared__ float fsm[];
    float* Wb = fsm;               // [128][65]
    float* hh = fsm + 128*65;      // [64][64]
    const int z = blockIdx.z;
    const float* W   = (z==0) ? wq : (z==1) ? wk : (z==2) ? wv : wo;
    const float* hhw = (z==0) ? hqw : (z==1) ? hkw : nullptr;
    __half* dst = (z==3) ? woT : wT;
    const int rowOff = (z==0) ? 0 : (z==1) ? 1024 : (z==2) ? 2048 : 0;

    const int h = blockIdx.x, kb = blockIdx.y;
    const int tid = threadIdx.x;
    for (int i = tid; i < 8192; i += 256) {
        int r = i >> 6, d = i & 63;
        Wb[r*65 + d] = W[(size_t)(kb*128 + r)*D_ + h*64 + d];
    }
    if (hhw)
        for (int i = tid; i < 4096; i += 256) hh[i] = hhw[i];
    __syncthreads();

    const int kk = tid & 127;
    const int e0 = (tid >> 7) * 32;
    float acc[32];
    if (hhw) {
        #pragma unroll
        for (int e = 0; e < 32; e++) acc[e] = 0.f;
        for (int d = 0; d < 64; d++) {
            float wv2 = Wb[kk*65 + d];
            #pragma unroll
            for (int e = 0; e < 32; e++)
                acc[e] = fmaf(wv2, hh[(e0+e)*64 + d], acc[e]);
        }
    } else {
        #pragma unroll
        for (int e = 0; e < 32; e++) acc[e] = Wb[kk*65 + e0 + e];
    }
    #pragma unroll
    for (int e = 0; e < 32; e++) {
        size_t idx = (size_t)(rowOff + h*64 + e0 + e)*D_ + kb*128 + kk;
        dst[idx] = __float2half_rn(acc[e]);
    }
}

// ---------------- fused add + RMSNorm -> resid + fp16 x ----------------------
__global__ __launch_bounds__(256)
void addnorm_kernel(const float* __restrict__ hs, const float* __restrict__ res,
                    const float* __restrict__ w, float* __restrict__ resid_out,
                    __half* __restrict__ xh)
{
    __shared__ float red[8];
    const int row = blockIdx.x;
    const int t = threadIdx.x;
    const float4* h4 = (const float4*)(hs  + (size_t)row*D_);
    const float4* r4 = (const float4*)(res + (size_t)row*D_);
    float4*      ro4 = (float4*)(resid_out + (size_t)row*D_);

    float4 h = h4[t], r = r4[t];
    float4 s = make_float4(h.x+r.x, h.y+r.y, h.z+r.z, h.w+r.w);
    ro4[t] = s;
    float ss = s.x*s.x + s.y*s.y + s.z*s.z + s.w*s.w;
    #pragma unroll
    for (int o = 16; o; o >>= 1) ss += __shfl_xor_sync(0xffffffffu, ss, o);
    if ((t & 31) == 0) red[t >> 5] = ss;
    __syncthreads();
    float tot = 0.f;
    #pragma unroll
    for (int i = 0; i < 8; i++) tot += red[i];
    float rstd = rsqrtf(tot * (1.0f/1024.0f) + 1e-5f);
    float4 wv = ((const float4*)w)[t];
    size_t idx = (size_t)row*D_ + t*4;
    *(__half2*)(xh+idx)   = __halves2half2(__float2half_rn(s.x*rstd*wv.x),
                                           __float2half_rn(s.y*rstd*wv.y));
    *(__half2*)(xh+idx+2) = __halves2half2(__float2half_rn(s.z*rstd*wv.z),
                                           __float2half_rn(s.w*rstd*wv.w));
}

// ---------------- fp16 fused QKV GEMM + hedgehog epilogue ---------------------
#define PITCH 40
#define MAT_BYTES (128*PITCH*2)          // 10240
#define STAGEB (2*MAT_BYTES)             // 20480
#define GSMEM (4*STAGEB)                 // 81920

__global__ __launch_bounds__(256, 2)
void gemm_qkv(const __half* __restrict__ Ah, const __half* __restrict__ W,
              const float* __restrict__ biasq, const float* __restrict__ biask,
              __half* __restrict__ Qfh, __half* __restrict__ Kfh,
              __half* __restrict__ Vh)
{
    extern __shared__ __align__(16) char smem[];
    const uint32_t sbase = smem_u32(smem);
    const int tid = threadIdx.x, wid = tid >> 5, lane = tid & 31;
    const int bx = blockIdx.x, by = blockIdx.y;
    const int wm = wid & 1, wn = wid >> 1;

    const int lrow = tid >> 1;
    const int lc   = (tid & 1) * 2;
    const size_t gA = (size_t)(by*128 + lrow) * D_;
    const size_t gB = (size_t)(bx*128 + lrow) * D_;
    const uint32_t sRow = (uint32_t)lrow * 80;

    float acc[4][4][4];
    #pragma unroll
    for (int i = 0; i < 4; i++)
        #pragma unroll
        for (int j = 0; j < 4; j++)
            #pragma unroll
            for (int l = 0; l < 4; l++) acc[i][j][l] = 0.f;

    #define PREFETCH(kt, buf) do {                                              \
        const int k0 = (kt) * 32;                                               \
        const uint32_t b0 = sbase + (uint32_t)(buf) * STAGEB;                   \
        _Pragma("unroll")                                                       \
        for (int u = 0; u < 2; u++) {                                           \
            const int c = lc + u;                                               \
            const uint32_t so = sRow + (uint32_t)c * 16;                        \
            const size_t go = (size_t)k0 + c * 8;                               \
            cp_async16(b0 + 0*MAT_BYTES + so, Ah + gA + go);                    \
            cp_async16(b0 + 1*MAT_BYTES + so, W  + gB + go);                    \
        }                                                                       \
        cp_commit();                                                            \
    } while (0)

    PREFETCH(0, 0);
    PREFETCH(1, 1);
    PREFETCH(2, 2);

    const uint32_t aRow = (uint32_t)(wm*64 + (lane & 15)) * 80 + (uint32_t)(lane >> 4) * 16;
    const uint32_t bRow = (uint32_t)(wn*32 + ((lane >> 4) & 1)*8 + (lane & 7)) * 80
                        + (uint32_t)((lane >> 3) & 1) * 16;

    const int TILES = D_ / 32;   // 32
    int buf = 0;
    #pragma unroll 1
    for (int kt = 0; kt < TILES; kt++) {
        if (kt >= TILES - 3) cp_wait<0>(); else cp_wait<2>();
        __syncthreads();
        if (kt + 3 < TILES) {
            int b3 = buf + 3; if (b3 >= 4) b3 -= 4;
            PREFETCH(kt + 3, b3);
        }
        const uint32_t sb = sbase + (uint32_t)buf * STAGEB;

        #pragma unroll
        for (int kk = 0; kk < 2; kk++) {
            const uint32_t koff = (uint32_t)kk * 32;
            uint32_t bw[2][4];
            #pragma unroll
            for (int nt2 = 0; nt2 < 2; nt2++) {
                const uint32_t ba = bRow + (uint32_t)nt2 * 16 * 80 + koff;
                ldm_x4(sb + 1*MAT_BYTES + ba, bw[nt2][0], bw[nt2][1], bw[nt2][2], bw[nt2][3]);
            }
            #pragma unroll
            for (int mt = 0; mt < 4; mt++) {
                const uint32_t aa = aRow + (uint32_t)mt * 16 * 80 + koff;
                uint32_t ah[4];
                ldm_x4(sb + aa, ah[0], ah[1], ah[2], ah[3]);
                #pragma unroll
                for (int nt = 0; nt < 4; nt++) {
                    const uint32_t* bp = &bw[nt >> 1][(nt & 1) * 2];
                    float* d = acc[mt][nt];
                    mma16816h(d[0], d[1], d[2], d[3], ah[0], ah[1], ah[2], ah[3], bp[0], bp[1]);
                }
            }
        }
        buf++; if (buf == 4) buf = 0;
    }
    #undef PREFETCH
    __syncthreads();    // smem reuse below

    const int g = lane >> 2, tq = lane & 3;

    if (bx < 16) {
        const int isQ = (bx < 8);
        const float* bias = isQ ? biasq : biask;
        const float scale = isQ ? 0.08838834764831845f : 1.0f;
        __half* fh = isQ ? Qfh : Kfh;
        float* smax = (float*)smem;
        float* ssum = smax + 512;
        #pragma unroll
        for (int mt = 0; mt < 4; mt++) {
            float pm0 = 0.f, pm1 = 0.f;
            #pragma unroll
            for (int nt = 0; nt < 4; nt++) {
                const int cb = (wn*32 + nt*8 + tq*2) & 63;
                const float b0 = bias[cb], b1 = bias[cb + 1];
                float* d = acc[mt][nt];
                d[0] += b0; d[1] += b1; d[2] += b0; d[3] += b1;
                pm0 = fmaxf(pm0, fmaxf(fabsf(d[0]), fabsf(d[1])));
                pm1 = fmaxf(pm1, fmaxf(fabsf(d[2]), fabsf(d[3])));
            }
            pm0 = fmaxf(pm0, __shfl_xor_sync(0xffffffffu, pm0, 1));
            pm0 = fmaxf(pm0, __shfl_xor_sync(0xffffffffu, pm0, 2));
            pm1 = fmaxf(pm1, __shfl_xor_sync(0xffffffffu, pm1, 1));
            pm1 = fmaxf(pm1, __shfl_xor_sync(0xffffffffu, pm1, 2));
            if (tq == 0) {
                smax[wn*128 + wm*64 + mt*16 + g]     = pm0;
                smax[wn*128 + wm*64 + mt*16 + g + 8] = pm1;
            }
        }
        __syncthreads();
        float mrow[4][2];
        #pragma unroll
        for (int mt = 0; mt < 4; mt++) {
            #pragma unroll
            for (int half = 0; half < 2; half++) {
                const int r = wm*64 + mt*16 + g + half*8;
                mrow[mt][half] = fmaxf(smax[wn*128 + r], smax[(wn^1)*128 + r]);
            }
        }
        #pragma unroll
        for (int mt = 0; mt < 4; mt++) {
            float s0 = 0.f, s1 = 0.f;
            #pragma unroll
            for (int nt = 0; nt < 4; nt++) {
                const float* d = acc[mt][nt];
                s0 += __expf(d[0]-mrow[mt][0]) + __expf(-d[0]-mrow[mt][0])
                    + __expf(d[1]-mrow[mt][0]) + __expf(-d[1]-mrow[mt][0]);
                s1 += __expf(d[2]-mrow[mt][1]) + __expf(-d[2]-mrow[mt][1])
                    + __expf(d[3]-mrow[mt][1]) + __expf(-d[3]-mrow[mt][1]);
            }
            s0 += __shfl_xor_sync(0xffffffffu, s0, 1);
            s0 += __shfl_xor_sync(0xffffffffu, s0, 2);
            s1 += __shfl_xor_sync(0xffffffffu, s1, 1);
            s1 += __shfl_xor_sync(0xffffffffu, s1, 2);
            if (tq == 0) {
                ssum[wn*128 + wm*64 + mt*16 + g]     = s0;
                ssum[wn*128 + wm*64 + mt*16 + g + 8] = s1;
            }
        }
        __syncthreads();
        const int hloc = (bx & 7)*2 + (wn >> 1);
        #pragma unroll
        for (int mt = 0; mt < 4; mt++) {
            #pragma unroll
            for (int half = 0; half < 2; half++) {
                const int r = wm*64 + mt*16 + g + half*8;
                const float z = ssum[wn*128 + r] + ssum[(wn^1)*128 + r];
                const float inv = scale / z;
                const float mm = mrow[mt][half];
                const int rowg = by*128 + r;
                const int bb = rowg >> 11, tt = rowg & 2047;
                const size_t base = ((size_t)(bb*H_ + hloc)*T_ + tt)*F_;
                #pragma unroll
                for (int nt = 0; nt < 4; nt++) {
                    const int f = (wn*32 + nt*8 + tq*2) & 63;
                    const float y0 = acc[mt][nt][half*2], y1 = acc[mt][nt][half*2+1];
                    const float p0 = __expf(y0 - mm)*inv,  p1 = __expf(y1 - mm)*inv;
                    const float n0 = __expf(-y0 - mm)*inv, n1 = __expf(-y1 - mm)*inv;
                    *(__half2*)(fh + base + f) =
                        __halves2half2(__float2half_rn(p0), __float2half_rn(p1));
                    *(__half2*)(fh + base + 64 + f) =
                        __halves2half2(__float2half_rn(n0), __float2half_rn(n1));
                }
            }
        }
    } else {
        const int colbase = (bx - 16)*128;
        #pragma unroll
        for (int mt = 0; mt < 4; mt++) {
            const int r0 = by*128 + wm*64 + mt*16 + g;
            #pragma unroll
            for (int nt = 0; nt < 4; nt++) {
                const int col = colbase + wn*32 + nt*8 + tq*2;
                float* d = acc[mt][nt];
                *(__half2*)(Vh + (size_t)r0*D_ + col) =
                    __halves2half2(__float2half_rn(d[0]), __float2half_rn(d[1]));
                *(__half2*)(Vh + (size_t)(r0+8)*D_ + col) =
                    __halves2half2(__float2half_rn(d[2]), __float2half_rn(d[3]));
            }
        }
    }
}

// ---------------- fp16 GEMM (fp32 out; o-projection) --------------------------
__global__ __launch_bounds__(256, 2)
void gemm_o(const __half* __restrict__ Ah, const __half* __restrict__ W,
            float* __restrict__ Cout)
{
    extern __shared__ __align__(16) char smem[];
    const uint32_t sbase = smem_u32(smem);
    const int tid = threadIdx.x, wid = tid >> 5, lane = tid & 31;
    const int bx = blockIdx.x, by = blockIdx.y;
    const int wm = wid & 1, wn = wid >> 1;

    const int lrow = tid >> 1;
    const int lc   = (tid & 1) * 2;
    const size_t gA = (size_t)(by*128 + lrow) * D_;
    const size_t gB = (size_t)(bx*128 + lrow) * D_;
    const uint32_t sRow = (uint32_t)lrow * 80;

    float acc[4][4][4];
    #pragma unroll
    for (int i = 0; i < 4; i++)
        #pragma unroll
        for (int j = 0; j < 4; j++)
            #pragma unroll
            for (int l = 0; l < 4; l++) acc[i][j][l] = 0.f;

    #define PREFETCH(kt, buf) do {                                              \
        const int k0 = (kt) * 32;                                               \
        const uint32_t b0 = sbase + (uint32_t)(buf) * STAGEB;                   \
        _Pragma("unroll")                                                       \
        for (int u = 0; u < 2; u++) {                                           \
            const int c = lc + u;                                               \
            const uint32_t so = sRow + (uint32_t)c * 16;                        \
            const size_t go = (size_t)k0 + c * 8;                               \
            cp_async16(b0 + 0*MAT_BYTES + so, Ah + gA + go);                    \
            cp_async16(b0 + 1*MAT_BYTES + so, W  + gB + go);                    \
        }                                                                       \
        cp_commit();                                                            \
    } while (0)

    PREFETCH(0, 0);
    PREFETCH(1, 1);
    PREFETCH(2, 2);

    const uint32_t aRow = (uint32_t)(wm*64 + (lane & 15)) * 80 + (uint32_t)(lane >> 4) * 16;
    const uint32_t bRow = (uint32_t)(wn*32 + ((lane >> 4) & 1)*8 + (lane & 7)) * 80
                        + (uint32_t)((lane >> 3) & 1) * 16;

    const int TILES = D_ / 32;
    int buf = 0;
    #pragma unroll 1
    for (int kt = 0; kt < TILES; kt++) {
        if (kt >= TILES - 3) cp_wait<0>(); else cp_wait<2>();
        __syncthreads();
        if (kt + 3 < TILES) {
            int b3 = buf + 3; if (b3 >= 4) b3 -= 4;
            PREFETCH(kt + 3, b3);
        }
        const uint32_t sb = sbase + (uint32_t)buf * STAGEB;

        #pragma unroll
        for (int kk = 0; kk < 2; kk++) {
            const uint32_t koff = (uint32_t)kk * 32;
            uint32_t bw[2][4];
            #pragma unroll
            for (int nt2 = 0; nt2 < 2; nt2++) {
                const uint32_t ba = bRow + (uint32_t)nt2 * 16 * 80 + koff;
                ldm_x4(sb + 1*MAT_BYTES + ba, bw[nt2][0], bw[nt2][1], bw[nt2][2], bw[nt2][3]);
            }
            #pragma unroll
            for (int mt = 0; mt < 4; mt++) {
                const uint32_t aa = aRow + (uint32_t)mt * 16 * 80 + koff;
                uint32_t ah[4];
                ldm_x4(sb + aa, ah[0], ah[1], ah[2], ah[3]);
                #pragma unroll
                for (int nt = 0; nt < 4; nt++) {
                    const uint32_t* bp = &bw[nt >> 1][(nt & 1) * 2];
                    float* d = acc[mt][nt];
                    mma16816h(d[0], d[1], d[2], d[3], ah[0], ah[1], ah[2], ah[3], bp[0], bp[1]);
                }
            }
        }
        buf++; if (buf == 4) buf = 0;
    }
    #undef PREFETCH

    const int g = lane >> 2, tq = lane & 3;
    #pragma unroll
    for (int mt = 0; mt < 4; mt++) {
        const int r0 = by*128 + wm*64 + mt*16 + g;
        #pragma unroll
        for (int nt = 0; nt < 4; nt++) {
            const int col = bx*128 + wn*32 + nt*8 + tq*2;
            float* d = acc[mt][nt];
            *(float2*)(Cout + (size_t)r0*D_ + col)     = make_float2(d[0], d[1]);
            *(float2*)(Cout + (size_t)(r0+8)*D_ + col) = make_float2(d[2], d[3]);
        }
    }
}

// ---------------- phase A: kv^T[d][f] = sum_c v[c,d] k[c,f] -------------------
#define CKV_K   0u
#define CKV_V   17408u
#define CKV_SMEM 26624u

__global__ __launch_bounds__(256, 3)
void chunk_kv_kernel(const __half* __restrict__ kfh,
                     const __half* __restrict__ vh,
                     __half* __restrict__ kvT)
{
    extern __shared__ __align__(16) char smem[];
    const uint32_t sb = smem_u32(smem);
    const int blk = blockIdx.x;
    const int n = blk & 31, bh = blk >> 5;
    const int b = bh >> 4, h = bh & 15;
    const int tid = threadIdx.x, wid = tid >> 5, lane = tid & 31;

    // cp.async staging (natural layouts)
    {
        const int c = tid >> 2, fg = (tid & 3) * 32;
        const size_t src = ((size_t)bh*T_ + n*C_ + c)*F_ + fg;
        const uint32_t dk = sb + CKV_K + c*272 + fg*2;
        #pragma unroll
        for (int q = 0; q < 4; q++) cp_async16(dk + q*16, kfh + src + q*8);
    }
    {
        const int c = tid >> 2, dg = (tid & 3) * 16;
        const size_t src = ((size_t)(b*T_) + n*C_ + c)*D_ + h*HD_ + dg;
        const uint32_t dv = sb + CKV_V + c*144 + dg*2;
        #pragma unroll
        for (int q = 0; q < 2; q++) cp_async16(dv + q*16, vh + src + q*8);
    }
    cp_commit();
    cp_wait<0>();
    __syncthreads();

    const int wm = wid & 3, wn = wid >> 2;
    float acc[8][4];
    #pragma unroll
    for (int i = 0; i < 8; i++)
        #pragma unroll
        for (int j = 0; j < 4; j++) acc[i][j] = 0.f;

    const uint32_t aBase = sb + CKV_V
        + (uint32_t)(((lane >> 4) & 1)*8 + (lane & 7)) * 144
        + (uint32_t)(wm*16 + ((lane >> 3) & 1)*8) * 2;
    const uint32_t bBase = sb + CKV_K
        + (uint32_t)(((lane >> 3) & 1)*8 + (lane & 7)) * 272
        + (uint32_t)(wn*64 + ((lane >> 4) & 1)*8) * 2;

    #pragma unroll
    for (int ks = 0; ks < 4; ks++) {
        uint32_t ah[4];
        ldm_x4t(aBase + (uint32_t)ks*16*144, ah[0], ah[1], ah[2], ah[3]);
        uint32_t bw[4][4];
        #pragma unroll
        for (int p = 0; p < 4; p++) {
            ldm_x4t(bBase + (uint32_t)ks*16*272 + (uint32_t)p*32,
                    bw[p][0], bw[p][1], bw[p][2], bw[p][3]);
        }
        #pragma unroll
        for (int nt = 0; nt < 8; nt++) {
            const uint32_t* bp = &bw[nt >> 1][(nt & 1)*2];
            float* d = acc[nt];
            mma16816h(d[0], d[1], d[2], d[3], ah[0], ah[1], ah[2], ah[3], bp[0], bp[1]);
        }
    }
    const int g = lane >> 2, tq = lane & 3;
    __half* out = kvT + (size_t)blk * (F_*HD_);
    #pragma unroll
    for (int nt = 0; nt < 8; nt++) {
        const int f = wn*64 + nt*8 + tq*2;
        const int d0 = wm*16 + g;
        *(__half2*)(out + (size_t)d0*F_ + f) =
            __halves2half2(__float2half_rn(acc[nt][0]), __float2half_rn(acc[nt][1]));
        *(__half2*)(out + (size_t)(d0+8)*F_ + f) =
            __halves2half2(__float2half_rn(acc[nt][2]), __float2half_rn(acc[nt][3]));
    }
}

// ---------------- phase B: exclusive cumsum (fp32 acc) -> fp16, half2 --------
__global__ __launch_bounds__(1024)
void kv_scan_kernel(const __half2* __restrict__ kvT, __half2* __restrict__ ST)
{
    const int blk = blockIdx.x;                   // 256: bh = blk>>2, seg = blk&3
    const int bh = blk >> 2, seg = blk & 3;
    const int e = seg*1024 + threadIdx.x;         // half2 index, 4096 per plane
    size_t base = (size_t)bh * N_ * (F_*HD_/2) + e;
    float2 acc = make_float2(0.f, 0.f);
    for (int n = 0; n < N_; n++) {
        size_t idx = base + (size_t)n * (F_*HD_/2);
        ST[idx] = __floats2half2_rn(acc.x, acc.y);
        float2 v = __half22float2(kvT[idx]);
        acc.x += v.x; acc.y += v.y;
    }
}

// ---------------- phase C: out = q@S_excl + tril(q@k^T)@v ---------------------
// ST gets its own region, staged by cp.async at kernel start (group overlaps
// the scores phase). q,k [c][f] p272; v [c][d] p144; scores [c][m] p144.
#define CO_Q   0u          // 17408
#define CO_K   17408u      // 17408
#define CO_V   34816u      // 9216
#define CO_SC  44032u      // 9216
#define CO_ST  53248u      // 17408
#define CO_SMEM 70656u

__global__ __launch_bounds__(256, 3)
void chunk_out_kernel(const __half* __restrict__ qfh,
                      const __half* __restrict__ kfh,
                      const __half* __restrict__ vh,
                      const __half* __restrict__ ST,
                      __half* __restrict__ oh)
{
    extern __shared__ __align__(16) char smem[];
    const uint32_t sb = smem_u32(smem);
    const int blk = blockIdx.x;
    const int n = blk & 31, bh = blk >> 5;
    const int b = bh >> 4, h = bh & 15;
    const int tid = threadIdx.x, wid = tid >> 5, lane = tid & 31;

    // group 1: q, k, v
    {
        const int c = tid >> 2, fg = (tid & 3) * 32;
        const size_t src = ((size_t)bh*T_ + n*C_ + c)*F_ + fg;
        const uint32_t dq = sb + CO_Q + c*272 + fg*2;
        const uint32_t dk = sb + CO_K + c*272 + fg*2;
        #pragma unroll
        for (int q = 0; q < 4; q++) {
            cp_async16(dq + q*16, qfh + src + q*8);
            cp_async16(dk + q*16, kfh + src + q*8);
        }
    }
    {
        const int c = tid >> 2, dg = (tid & 3) * 16;
        const size_t src = ((size_t)(b*T_) + n*C_ + c)*D_ + h*HD_ + dg;
        const uint32_t dv = sb + CO_V + c*144 + dg*2;
        #pragma unroll
        for (int q = 0; q < 2; q++) cp_async16(dv + q*16, vh + src + q*8);
    }
    cp_commit();
    // group 2: ST (overlaps with scores compute)
    {
        const int d = tid >> 2, fg = (tid & 3) * 32;
        const size_t src = (size_t)blk*(F_*HD_) + d*F_ + fg;
        const uint32_t ds = sb + CO_ST + d*272 + fg*2;
        #pragma unroll
        for (int q = 0; q < 4; q++) cp_async16(ds + q*16, ST + src + q*8);
    }
    cp_commit();
    cp_wait<1>();       // q,k,v ready; ST still in flight
    __syncthreads();

    const int wm = wid & 3, wn = wid >> 2;
    const int g = lane >> 2, tq = lane & 3;

    const uint32_t aQ = sb + CO_Q + (uint32_t)(wm*16 + (lane & 15))*272 + (uint32_t)(lane >> 4)*16;
    const uint32_t bK = sb + CO_K + (uint32_t)(wn*32 + ((lane >> 4) & 1)*8 + (lane & 7))*272
                      + (uint32_t)((lane >> 3) & 1)*16;

    // ---- scores = q @ k^T ----
    float sacc[4][4];
    #pragma unroll
    for (int i = 0; i < 4; i++)
        #pragma unroll
        for (int j = 0; j < 4; j++) sacc[i][j] = 0.f;

    #pragma unroll
    for (int ks = 0; ks < 8; ks++) {
        const uint32_t koff = (uint32_t)ks*32;
        uint32_t ah[4];
        ldm_x4(aQ + koff, ah[0], ah[1], ah[2], ah[3]);
        uint32_t bw[2][4];
        #pragma unroll
        for (int p = 0; p < 2; p++) {
            const uint32_t ba = bK + (uint32_t)p*16*272 + koff;
            ldm_x4(ba, bw[p][0], bw[p][1], bw[p][2], bw[p][3]);
        }
        #pragma unroll
        for (int nt = 0; nt < 4; nt++) {
            const uint32_t* bp = &bw[nt >> 1][(nt & 1)*2];
            float* d = sacc[nt];
            mma16816h(d[0], d[1], d[2], d[3], ah[0], ah[1], ah[2], ah[3], bp[0], bp[1]);
        }
    }
    #pragma unroll
    for (int nt = 0; nt < 4; nt++) {
        const int colb = wn*32 + nt*8 + tq*2;
        const int r0 = wm*16 + g, r1 = r0 + 8;
        float v00 = (colb     <= r0) ? sacc[nt][0] : 0.f;
        float v01 = (colb + 1 <= r0) ? sacc[nt][1] : 0.f;
        float v10 = (colb     <= r1) ? sacc[nt][2] : 0.f;
        float v11 = (colb + 1 <= r1) ? sacc[nt][3] : 0.f;
        *(__half2*)(smem + CO_SC + r0*144 + colb*2) =
            __halves2half2(__float2half_rn(v00), __float2half_rn(v01));
        *(__half2*)(smem + CO_SC + r1*144 + colb*2) =
            __halves2half2(__float2half_rn(v10), __float2half_rn(v11));
    }
    cp_wait<0>();       // ST landed
    __syncthreads();    // scores + ST visible to all

    // ---- out = q @ S_excl + scores @ v ----
    float oacc[4][4];
    #pragma unroll
    for (int i = 0; i < 4; i++)
        #pragma unroll
        for (int j = 0; j < 4; j++) oacc[i][j] = 0.f;

    const uint32_t bS = sb + CO_ST + (uint32_t)(wn*32 + ((lane >> 4) & 1)*8 + (lane & 7))*272
                      + (uint32_t)((lane >> 3) & 1)*16;
    #pragma unroll
    for (int ks = 0; ks < 8; ks++) {     // inter
        const uint32_t koff = (uint32_t)ks*32;
        uint32_t ah[4];
        ldm_x4(aQ + koff, ah[0], ah[1], ah[2], ah[3]);
        uint32_t bw[2][4];
        #pragma unroll
        for (int p = 0; p < 2; p++) {
            const uint32_t ba = bS + (uint32_t)p*16*272 + koff;
            ldm_x4(ba, bw[p][0], bw[p][1], bw[p][2], bw[p][3]);
        }
        #pragma unroll
        for (int nt = 0; nt < 4; nt++) {
            const uint32_t* bp = &bw[nt >> 1][(nt & 1)*2];
            float* d = oacc[nt];
            mma16816h(d[0], d[1], d[2], d[3], ah[0], ah[1], ah[2], ah[3], bp[0], bp[1]);
        }
    }
    {   // intra: A = scores (normal), B = v via trans
        const uint32_t aS = sb + CO_SC + (uint32_t)(wm*16 + (lane & 15))*144
                          + (uint32_t)(lane >> 4)*16;
        const uint32_t bV = sb + CO_V
            + (uint32_t)(((lane >> 3) & 1)*8 + (lane & 7)) * 144
            + (uint32_t)(wn*32 + ((lane >> 4) & 1)*8) * 2;
        #pragma unroll
        for (int ks = 0; ks < 4; ks++) {
            uint32_t ah[4];
            ldm_x4(aS + (uint32_t)ks*32, ah[0], ah[1], ah[2], ah[3]);
            uint32_t bw[2][4];
            #pragma unroll
            for (int p = 0; p < 2; p++) {
                ldm_x4t(bV + (uint32_t)ks*16*144 + (uint32_t)p*32,
                        bw[p][0], bw[p][1], bw[p][2], bw[p][3]);
            }
            #pragma unroll
            for (int nt = 0; nt < 4; nt++) {
                const uint32_t* bp = &bw[nt >> 1][(nt & 1)*2];
                float* d = oacc[nt];
                mma16816h(d[0], d[1], d[2], d[3], ah[0], ah[1], ah[2], ah[3], bp[0], bp[1]);
            }
        }
    }

    // write o single fp16 in [B,T,H*HD] layout
    #pragma unroll
    for (int nt = 0; nt < 4; nt++) {
        const int dcol = wn*32 + nt*8 + tq*2;
        const int r0 = wm*16 + g;
        #pragma unroll
        for (int half = 0; half < 2; half++) {
            const int r = r0 + half*8;
            const size_t oidx = ((size_t)(b*T_) + n*C_ + r)*D_ + h*HD_ + dcol;
            *(__half2*)(oh + oidx) =
                __halves2half2(__float2half_rn(oacc[nt][half*2]),
                               __float2half_rn(oacc[nt][half*2+1]));
        }
    }
}

// ---------------- launcher ----------------------------------------------------
extern "C" void kernel_launch(void* const* d_in, const int* in_sizes, int n_in,
                              void* d_out, int out_size)
{
    const float* hs   = (const float*)d_in[0];
    const float* res  = (const float*)d_in[1];
    const float* nw   = (const float*)d_in[2];
    const float* w_q  = (const float*)d_in[3];
    const float* w_k  = (const float*)d_in[4];
    const float* w_v  = (const float*)d_in[5];
    const float* w_o  = (const float*)d_in[6];
    const float* hqw  = (const float*)d_in[7];
    const float* hqb  = (const float*)d_in[8];
    const float* hkw  = (const float*)d_in[9];
    const float* hkb  = (const float*)d_in[10];
    float* out = (float*)d_out;

    __half *pkv, *pxh, *poh, *pwT, *pwo, *pqfh, *pkfh, *pvh, *pST;
    cudaGetSymbolAddress((void**)&pkv,  g_kv);
    cudaGetSymbolAddress((void**)&pxh,  g_xh);
    cudaGetSymbolAddress((void**)&poh,  g_oh);
    cudaGetSymbolAddress((void**)&pwT,  g_wT);
    cudaGetSymbolAddress((void**)&pwo,  g_woT);
    cudaGetSymbolAddress((void**)&pqfh, g_qfh);
    cudaGetSymbolAddress((void**)&pkfh, g_kfh);
    cudaGetSymbolAddress((void**)&pvh,  g_vh);
    cudaGetSymbolAddress((void**)&pST,  g_ST);

    const int fsmem = (128*65 + 64*64) * sizeof(float);   // 49664
    cudaFuncSetAttribute(weightprep_kernel,
                         cudaFuncAttributeMaxDynamicSharedMemorySize, fsmem);
    cudaFuncSetAttribute(gemm_qkv,
                         cudaFuncAttributeMaxDynamicSharedMemorySize, GSMEM);
    cudaFuncSetAttribute(gemm_o,
                         cudaFuncAttributeMaxDynamicSharedMemorySize, GSMEM);
    cudaFuncSetAttribute(chunk_kv_kernel,
                         cudaFuncAttributeMaxDynamicSharedMemorySize, CKV_SMEM);
    cudaFuncSetAttribute(chunk_out_kernel,
                         cudaFuncAttributeMaxDynamicSharedMemorySize, CO_SMEM);

    // 1) weight prep (fold hedgehog into q/k; transpose v, o) -> fp16
    weightprep_kernel<<<dim3(16, 8, 4), 256, fsmem>>>(w_q, w_k, w_v, w_o, hqw, hkw, pwT, pwo);

    // 2) fused add + RMSNorm
    addnorm_kernel<<<BT_, 256>>>(hs, res, nw, out + (size_t)BT_*D_, pxh);

    // 3) fused QKV projection + hedgehog epilogue
    dim3 qkvgrid(24, BT_/128);
    gemm_qkv<<<qkvgrid, 256, GSMEM>>>(pxh, pwT, hqb, hkb, pqfh, pkfh, pvh);

    // 4) chunked linear attention
    chunk_kv_kernel<<<NCHUNK_, 256, CKV_SMEM>>>(pkfh, pvh, pkv);
    kv_scan_kernel<<<256, 1024>>>((const __half2*)pkv, (__half2*)pST);
    chunk_out_kernel<<<NCHUNK_, 256, CO_SMEM>>>(pqfh, pkfh, pvh, pST, poh);

    // 5) output projection
    gemm_o<<<dim3(8, BT_/128), 256, GSMEM>>>(poh, pwo, out);
}